// round 1
// baseline (speedup 1.0000x reference)
#include <cuda_runtime.h>
#include <cuda_bf16.h>
#include <math.h>

// Problem constants
#define BB 4
#define SS 2048
#define DD 512
#define HH 8
#define HDD 64
#define DFF 1024
#define MROWS (BB * SS)   // 8192

// ---------------- scratch buffers (device globals; no allocation allowed) ----
__device__ float g_q [BB * SS * DD];
__device__ float g_k [BB * SS * DD];
__device__ float g_v [BB * SS * DD];
__device__ float g_av[BB * SS * DD];
__device__ float g_rs[BB * SS * DD];   // proj / ff output (reused)
__device__ float g_t1[BB * SS * DD];   // after first layernorm
__device__ float g_h [BB * SS * DFF];  // ffn hidden

// ============================================================================
// GEMM (NT): C[m][n] = bias[n] + sum_k A[m][k] * W[n][k];  optional ReLU.
// Tiles: BM=BN=128, BK=8, 256 threads, 8x8 per thread.
// ============================================================================
template<bool RELU>
__global__ void __launch_bounds__(256, 2)
gemm_nt_bias(const float* __restrict__ A, const float* __restrict__ W,
             const float* __restrict__ bias, float* __restrict__ C,
             int M, int N, int K)
{
    __shared__ float As[8][132];
    __shared__ float Ws[8][132];

    const int bm = blockIdx.y * 128;
    const int bn = blockIdx.x * 128;
    const int tid = threadIdx.x;
    const int tx = tid & 15;        // 0..15 (n)
    const int ty = tid >> 4;        // 0..15 (m)

    const int lr = tid >> 1;        // 0..127 load row
    const int lc = (tid & 1) * 4;   // 0 or 4 within BK=8

    const float* Ap = A + (size_t)(bm + lr) * K + lc;
    const float* Wp = W + (size_t)(bn + lr) * K + lc;

    float acc[8][8];
    #pragma unroll
    for (int i = 0; i < 8; i++)
        #pragma unroll
        for (int j = 0; j < 8; j++) acc[i][j] = 0.f;

    for (int kt = 0; kt < K; kt += 8) {
        float4 a4 = *(const float4*)(Ap + kt);
        float4 w4 = *(const float4*)(Wp + kt);
        __syncthreads();
        As[lc + 0][lr] = a4.x; As[lc + 1][lr] = a4.y;
        As[lc + 2][lr] = a4.z; As[lc + 3][lr] = a4.w;
        Ws[lc + 0][lr] = w4.x; Ws[lc + 1][lr] = w4.y;
        Ws[lc + 2][lr] = w4.z; Ws[lc + 3][lr] = w4.w;
        __syncthreads();

        #pragma unroll
        for (int kk = 0; kk < 8; kk++) {
            float ar[8], wr[8];
            *(float4*)&ar[0] = *(const float4*)&As[kk][ty * 8];
            *(float4*)&ar[4] = *(const float4*)&As[kk][ty * 8 + 4];
            *(float4*)&wr[0] = *(const float4*)&Ws[kk][tx * 8];
            *(float4*)&wr[4] = *(const float4*)&Ws[kk][tx * 8 + 4];
            #pragma unroll
            for (int i = 0; i < 8; i++)
                #pragma unroll
                for (int j = 0; j < 8; j++)
                    acc[i][j] += ar[i] * wr[j];
        }
    }

    float bs[8];
    #pragma unroll
    for (int j = 0; j < 8; j++) bs[j] = bias[bn + tx * 8 + j];

    #pragma unroll
    for (int i = 0; i < 8; i++) {
        float* cp = C + (size_t)(bm + ty * 8 + i) * N + bn + tx * 8;
        float o[8];
        #pragma unroll
        for (int j = 0; j < 8; j++) {
            float t = acc[i][j] + bs[j];
            if (RELU) t = fmaxf(t, 0.f);
            o[j] = t;
        }
        ((float4*)cp)[0] = *(float4*)&o[0];
        ((float4*)cp)[1] = *(float4*)&o[4];
    }
}

// ============================================================================
// Flash attention. Layout of Q/K/V/O: [B, S, H, HD] (head-interleaved in D).
// One block: 128 queries of one (b,h). Tiles of 128 keys. 256 threads.
// smem: Qt[64][128] (d-major), Kt[64][128], Vs[128][68], Ss[128][128].
// ============================================================================
#define ATT_SMEM_FLOATS (64 * 128 + 64 * 128 + 128 * 68 + 128 * 128)
#define ATT_SMEM_BYTES  (ATT_SMEM_FLOATS * 4)

__global__ void __launch_bounds__(256, 1)
attn_kernel(const float* __restrict__ Q, const float* __restrict__ K,
            const float* __restrict__ V, float* __restrict__ O)
{
    extern __shared__ float sm[];
    float* Qt = sm;                    // [64][128]
    float* Kt = Qt + 64 * 128;         // [64][128]
    float* Vs = Kt + 64 * 128;         // [128][68]
    float* Ss = Vs + 128 * 68;         // [128][128]

    const int tid = threadIdx.x;
    const int tx = tid & 15;           // 0..15
    const int ty = tid >> 4;           // 0..15
    const int b = blockIdx.y >> 3;
    const int h = blockIdx.y & 7;
    const size_t base = (size_t)b * SS * DD + (size_t)h * HDD;
    const int q0 = blockIdx.x * 128;
    const float scale = 0.125f;        // 1/sqrt(64)

    // load Q tile transposed (d-major), fold in softmax scale
    {
        const int r = tid >> 1;
        const int dh = (tid & 1) * 32;
        const float* qp = Q + base + (size_t)(q0 + r) * DD + dh;
        #pragma unroll
        for (int i = 0; i < 8; i++) {
            float4 t = *(const float4*)(qp + i * 4);
            Qt[(dh + i * 4 + 0) * 128 + r] = t.x * scale;
            Qt[(dh + i * 4 + 1) * 128 + r] = t.y * scale;
            Qt[(dh + i * 4 + 2) * 128 + r] = t.z * scale;
            Qt[(dh + i * 4 + 3) * 128 + r] = t.w * scale;
        }
    }

    float acc[8][4];
    float mrow[8], lrow[8];
    #pragma unroll
    for (int i = 0; i < 8; i++) {
        mrow[i] = -1e30f; lrow[i] = 0.f;
        #pragma unroll
        for (int d = 0; d < 4; d++) acc[i][d] = 0.f;
    }

    for (int kt = 0; kt < SS; kt += 128) {
        __syncthreads();   // previous AV phase done with Vs/Ss
        // load K (transposed) and V tiles
        {
            const int r = tid >> 1;
            const int dh = (tid & 1) * 32;
            const float* kp = K + base + (size_t)(kt + r) * DD + dh;
            const float* vp = V + base + (size_t)(kt + r) * DD + dh;
            #pragma unroll
            for (int i = 0; i < 8; i++) {
                float4 t = *(const float4*)(kp + i * 4);
                Kt[(dh + i * 4 + 0) * 128 + r] = t.x;
                Kt[(dh + i * 4 + 1) * 128 + r] = t.y;
                Kt[(dh + i * 4 + 2) * 128 + r] = t.z;
                Kt[(dh + i * 4 + 3) * 128 + r] = t.w;
            }
            #pragma unroll
            for (int i = 0; i < 8; i++)
                *(float4*)&Vs[r * 68 + dh + i * 4] = *(const float4*)(vp + i * 4);
        }
        __syncthreads();

        // scores: frag [8 rows (ty)] x [8 keys (tx)]
        float s[8][8];
        #pragma unroll
        for (int i = 0; i < 8; i++)
            #pragma unroll
            for (int j = 0; j < 8; j++) s[i][j] = 0.f;

        #pragma unroll 4
        for (int d = 0; d < 64; d++) {
            float qr[8], kr[8];
            *(float4*)&qr[0] = *(const float4*)&Qt[d * 128 + ty * 8];
            *(float4*)&qr[4] = *(const float4*)&Qt[d * 128 + ty * 8 + 4];
            *(float4*)&kr[0] = *(const float4*)&Kt[d * 128 + tx * 8];
            *(float4*)&kr[4] = *(const float4*)&Kt[d * 128 + tx * 8 + 4];
            #pragma unroll
            for (int i = 0; i < 8; i++)
                #pragma unroll
                for (int j = 0; j < 8; j++)
                    s[i][j] += qr[i] * kr[j];
        }

        // online softmax per row (16 lanes with same ty own a row set)
        #pragma unroll
        for (int i = 0; i < 8; i++) {
            float mx = s[i][0];
            #pragma unroll
            for (int j = 1; j < 8; j++) mx = fmaxf(mx, s[i][j]);
            #pragma unroll
            for (int o = 8; o >= 1; o >>= 1)
                mx = fmaxf(mx, __shfl_xor_sync(0xffffffffu, mx, o));
            float mnew = fmaxf(mrow[i], mx);
            float alpha = __expf(mrow[i] - mnew);
            mrow[i] = mnew;
            float rsum = 0.f;
            #pragma unroll
            for (int j = 0; j < 8; j++) {
                float p = __expf(s[i][j] - mnew);
                s[i][j] = p;
                rsum += p;
            }
            #pragma unroll
            for (int o = 8; o >= 1; o >>= 1)
                rsum += __shfl_xor_sync(0xffffffffu, rsum, o);
            lrow[i] = lrow[i] * alpha + rsum;
            #pragma unroll
            for (int d = 0; d < 4; d++) acc[i][d] *= alpha;
            *(float4*)&Ss[(ty * 8 + i) * 128 + tx * 8]     = *(float4*)&s[i][0];
            *(float4*)&Ss[(ty * 8 + i) * 128 + tx * 8 + 4] = *(float4*)&s[i][4];
        }
        __syncthreads();

        // AV: rows ty*8..+8, dims tx*4..+4
        #pragma unroll 2
        for (int j = 0; j < 128; j += 4) {
            float pv[8][4];
            #pragma unroll
            for (int i = 0; i < 8; i++)
                *(float4*)&pv[i][0] = *(const float4*)&Ss[(ty * 8 + i) * 128 + j];
            #pragma unroll
            for (int jj = 0; jj < 4; jj++) {
                float4 vv = *(const float4*)&Vs[(j + jj) * 68 + tx * 4];
                #pragma unroll
                for (int i = 0; i < 8; i++) {
                    float p = pv[i][jj];
                    acc[i][0] += p * vv.x;
                    acc[i][1] += p * vv.y;
                    acc[i][2] += p * vv.z;
                    acc[i][3] += p * vv.w;
                }
            }
        }
    }

    // epilogue: O[row][tx*4..+4] = acc / l
    #pragma unroll
    for (int i = 0; i < 8; i++) {
        float inv = 1.f / lrow[i];
        float o[4];
        #pragma unroll
        for (int d = 0; d < 4; d++) o[d] = acc[i][d] * inv;
        float* op = O + base + (size_t)(q0 + ty * 8 + i) * DD + tx * 4;
        *(float4*)op = *(float4*)&o[0];
    }
}

// ============================================================================
// out = LayerNorm(X + Yd) * g + be  ; one row (512 floats) per block, 128 thr.
// ============================================================================
__global__ void __launch_bounds__(128)
add_ln_kernel(const float* __restrict__ X, const float* __restrict__ Yd,
              const float* __restrict__ g, const float* __restrict__ be,
              float* __restrict__ out)
{
    __shared__ float red[4];
    const int row = blockIdx.x;
    const int tid = threadIdx.x;
    const int lane = tid & 31, wid = tid >> 5;

    float4 a = ((const float4*)(X  + (size_t)row * DD))[tid];
    float4 c = ((const float4*)(Yd + (size_t)row * DD))[tid];
    float v0 = a.x + c.x, v1 = a.y + c.y, v2 = a.z + c.z, v3 = a.w + c.w;

    float sum = v0 + v1 + v2 + v3;
    #pragma unroll
    for (int o = 16; o >= 1; o >>= 1) sum += __shfl_xor_sync(0xffffffffu, sum, o);
    if (lane == 0) red[wid] = sum;
    __syncthreads();
    sum = red[0] + red[1] + red[2] + red[3];
    float mu = sum * (1.f / DD);

    float d0 = v0 - mu, d1 = v1 - mu, d2 = v2 - mu, d3 = v3 - mu;
    float sq = d0 * d0 + d1 * d1 + d2 * d2 + d3 * d3;
    #pragma unroll
    for (int o = 16; o >= 1; o >>= 1) sq += __shfl_xor_sync(0xffffffffu, sq, o);
    __syncthreads();
    if (lane == 0) red[wid] = sq;
    __syncthreads();
    float var = (red[0] + red[1] + red[2] + red[3]) * (1.f / DD);
    float rs = rsqrtf(var + 1e-5f);

    float4 gv = ((const float4*)g)[tid];
    float4 bv = ((const float4*)be)[tid];
    float4 o4;
    o4.x = d0 * rs * gv.x + bv.x;
    o4.y = d1 * rs * gv.y + bv.y;
    o4.z = d2 * rs * gv.z + bv.z;
    o4.w = d3 * rs * gv.w + bv.w;
    ((float4*)(out + (size_t)row * DD))[tid] = o4;
}

// ============================================================================
extern "C" void kernel_launch(void* const* d_in, const int* in_sizes, int n_in,
                              void* d_out, int out_size)
{
    const float* x   = (const float*)d_in[0];
    const float* wq  = (const float*)d_in[1];
    const float* bq  = (const float*)d_in[2];
    const float* wk  = (const float*)d_in[3];
    const float* bk  = (const float*)d_in[4];
    const float* wv  = (const float*)d_in[5];
    const float* bv  = (const float*)d_in[6];
    const float* wo  = (const float*)d_in[7];
    const float* bo  = (const float*)d_in[8];
    const float* w1  = (const float*)d_in[9];
    const float* b1  = (const float*)d_in[10];
    const float* w2  = (const float*)d_in[11];
    const float* b2  = (const float*)d_in[12];
    const float* g1  = (const float*)d_in[13];
    const float* be1 = (const float*)d_in[14];
    const float* g2  = (const float*)d_in[15];
    const float* be2 = (const float*)d_in[16];
    float* out = (float*)d_out;

    float *q, *k, *v, *av, *rs, *t1, *hbuf;
    cudaGetSymbolAddress((void**)&q,    g_q);
    cudaGetSymbolAddress((void**)&k,    g_k);
    cudaGetSymbolAddress((void**)&v,    g_v);
    cudaGetSymbolAddress((void**)&av,   g_av);
    cudaGetSymbolAddress((void**)&rs,   g_rs);
    cudaGetSymbolAddress((void**)&t1,   g_t1);
    cudaGetSymbolAddress((void**)&hbuf, g_h);

    cudaFuncSetAttribute(attn_kernel,
                         cudaFuncAttributeMaxDynamicSharedMemorySize,
                         ATT_SMEM_BYTES);

    dim3 blk(256);
    dim3 grid_d(DD / 128, MROWS / 128);     // (4, 64)
    dim3 grid_f(DFF / 128, MROWS / 128);    // (8, 64)

    // QKV projections
    gemm_nt_bias<false><<<grid_d, blk>>>(x, wq, bq, q, MROWS, DD, DD);
    gemm_nt_bias<false><<<grid_d, blk>>>(x, wk, bk, k, MROWS, DD, DD);
    gemm_nt_bias<false><<<grid_d, blk>>>(x, wv, bv, v, MROWS, DD, DD);

    // attention
    dim3 agrid(SS / 128, BB * HH);          // (16, 32)
    attn_kernel<<<agrid, blk, ATT_SMEM_BYTES>>>(q, k, v, av);

    // output projection + residual + LN1
    gemm_nt_bias<false><<<grid_d, blk>>>(av, wo, bo, rs, MROWS, DD, DD);
    add_ln_kernel<<<MROWS, 128>>>(x, rs, g1, be1, t1);

    // FFN
    gemm_nt_bias<true ><<<grid_f, blk>>>(t1, w1, b1, hbuf, MROWS, DFF, DD);
    gemm_nt_bias<false><<<grid_d, blk>>>(hbuf, w2, b2, rs, MROWS, DD, DFF);
    add_ln_kernel<<<MROWS, 128>>>(t1, rs, g2, be2, out);
}

// round 2
// speedup vs baseline: 1.6243x; 1.6243x over previous
#include <cuda_runtime.h>
#include <cuda_bf16.h>
#include <math.h>

// Problem constants
#define BB 4
#define SS 2048
#define DD 512
#define HH 8
#define HDD 64
#define DFF 1024
#define MROWS (BB * SS)   // 8192

// ---------------- scratch buffers (device globals; no allocation allowed) ----
__device__ float g_q [BB * SS * DD];
__device__ float g_k [BB * SS * DD];
__device__ float g_v [BB * SS * DD];
__device__ float g_av[BB * SS * DD];
__device__ float g_rs[BB * SS * DD];   // proj / ff output (reused)
__device__ float g_t1[BB * SS * DD];   // after first layernorm
__device__ float g_h [BB * SS * DFF];  // ffn hidden

// ============================================================================
// GEMM (NT): C[m][n] = bias[n] + sum_k A[m][k] * W[n][k];  optional ReLU.
// Tiles: BM=BN=128, BK=8, 256 threads, 8x8 per thread.
// ============================================================================
template<bool RELU>
__global__ void __launch_bounds__(256, 2)
gemm_nt_bias(const float* __restrict__ A, const float* __restrict__ W,
             const float* __restrict__ bias, float* __restrict__ C,
             int M, int N, int K)
{
    __shared__ float As[8][132];
    __shared__ float Ws[8][132];

    const int bm = blockIdx.y * 128;
    const int bn = blockIdx.x * 128;
    const int tid = threadIdx.x;
    const int tx = tid & 15;        // 0..15 (n)
    const int ty = tid >> 4;        // 0..15 (m)

    const int lr = tid >> 1;        // 0..127 load row
    const int lc = (tid & 1) * 4;   // 0 or 4 within BK=8

    const float* Ap = A + (size_t)(bm + lr) * K + lc;
    const float* Wp = W + (size_t)(bn + lr) * K + lc;

    float acc[8][8];
    #pragma unroll
    for (int i = 0; i < 8; i++)
        #pragma unroll
        for (int j = 0; j < 8; j++) acc[i][j] = 0.f;

    for (int kt = 0; kt < K; kt += 8) {
        float4 a4 = *(const float4*)(Ap + kt);
        float4 w4 = *(const float4*)(Wp + kt);
        __syncthreads();
        As[lc + 0][lr] = a4.x; As[lc + 1][lr] = a4.y;
        As[lc + 2][lr] = a4.z; As[lc + 3][lr] = a4.w;
        Ws[lc + 0][lr] = w4.x; Ws[lc + 1][lr] = w4.y;
        Ws[lc + 2][lr] = w4.z; Ws[lc + 3][lr] = w4.w;
        __syncthreads();

        #pragma unroll
        for (int kk = 0; kk < 8; kk++) {
            float ar[8], wr[8];
            *(float4*)&ar[0] = *(const float4*)&As[kk][ty * 8];
            *(float4*)&ar[4] = *(const float4*)&As[kk][ty * 8 + 4];
            *(float4*)&wr[0] = *(const float4*)&Ws[kk][tx * 8];
            *(float4*)&wr[4] = *(const float4*)&Ws[kk][tx * 8 + 4];
            #pragma unroll
            for (int i = 0; i < 8; i++)
                #pragma unroll
                for (int j = 0; j < 8; j++)
                    acc[i][j] += ar[i] * wr[j];
        }
    }

    float bs[8];
    #pragma unroll
    for (int j = 0; j < 8; j++) bs[j] = bias[bn + tx * 8 + j];

    #pragma unroll
    for (int i = 0; i < 8; i++) {
        float* cp = C + (size_t)(bm + ty * 8 + i) * N + bn + tx * 8;
        float o[8];
        #pragma unroll
        for (int j = 0; j < 8; j++) {
            float t = acc[i][j] + bs[j];
            if (RELU) t = fmaxf(t, 0.f);
            o[j] = t;
        }
        ((float4*)cp)[0] = *(float4*)&o[0];
        ((float4*)cp)[1] = *(float4*)&o[4];
    }
}

// ============================================================================
// Flash attention. Layout of Q/K/V/O: [B, S, H, HD] (head-interleaved in D).
// One block: 128 queries of one (b,h). Tiles of 128 keys. 256 threads.
// smem: Qt[64][128] (d-major), Kt[64][128], Vs[128][68], Ss[128][128].
// ============================================================================
#define ATT_SMEM_FLOATS (64 * 128 + 64 * 128 + 128 * 68 + 128 * 128)
#define ATT_SMEM_BYTES  (ATT_SMEM_FLOATS * 4)

__global__ void __launch_bounds__(256, 1)
attn_kernel(const float* __restrict__ Q, const float* __restrict__ K,
            const float* __restrict__ V, float* __restrict__ O)
{
    extern __shared__ float sm[];
    float* Qt = sm;                    // [64][128]
    float* Kt = Qt + 64 * 128;         // [64][128]
    float* Vs = Kt + 64 * 128;         // [128][68]
    float* Ss = Vs + 128 * 68;         // [128][128]

    const int tid = threadIdx.x;
    const int tx = tid & 15;           // 0..15
    const int ty = tid >> 4;           // 0..15
    const int b = blockIdx.y >> 3;
    const int h = blockIdx.y & 7;
    const size_t base = (size_t)b * SS * DD + (size_t)h * HDD;
    const int q0 = blockIdx.x * 128;
    const float scale = 0.125f;        // 1/sqrt(64)

    // load Q tile transposed (d-major), fold in softmax scale
    {
        const int r = tid >> 1;
        const int dh = (tid & 1) * 32;
        const float* qp = Q + base + (size_t)(q0 + r) * DD + dh;
        #pragma unroll
        for (int i = 0; i < 8; i++) {
            float4 t = *(const float4*)(qp + i * 4);
            Qt[(dh + i * 4 + 0) * 128 + r] = t.x * scale;
            Qt[(dh + i * 4 + 1) * 128 + r] = t.y * scale;
            Qt[(dh + i * 4 + 2) * 128 + r] = t.z * scale;
            Qt[(dh + i * 4 + 3) * 128 + r] = t.w * scale;
        }
    }

    float acc[8][4];
    float mrow[8], lrow[8];
    #pragma unroll
    for (int i = 0; i < 8; i++) {
        mrow[i] = -1e30f; lrow[i] = 0.f;
        #pragma unroll
        for (int d = 0; d < 4; d++) acc[i][d] = 0.f;
    }

    for (int kt = 0; kt < SS; kt += 128) {
        __syncthreads();   // previous AV phase done with Vs/Ss
        // load K (transposed) and V tiles
        {
            const int r = tid >> 1;
            const int dh = (tid & 1) * 32;
            const float* kp = K + base + (size_t)(kt + r) * DD + dh;
            const float* vp = V + base + (size_t)(kt + r) * DD + dh;
            #pragma unroll
            for (int i = 0; i < 8; i++) {
                float4 t = *(const float4*)(kp + i * 4);
                Kt[(dh + i * 4 + 0) * 128 + r] = t.x;
                Kt[(dh + i * 4 + 1) * 128 + r] = t.y;
                Kt[(dh + i * 4 + 2) * 128 + r] = t.z;
                Kt[(dh + i * 4 + 3) * 128 + r] = t.w;
            }
            #pragma unroll
            for (int i = 0; i < 8; i++)
                *(float4*)&Vs[r * 68 + dh + i * 4] = *(const float4*)(vp + i * 4);
        }
        __syncthreads();

        // scores: frag [8 rows (ty)] x [8 keys (tx)]
        float s[8][8];
        #pragma unroll
        for (int i = 0; i < 8; i++)
            #pragma unroll
            for (int j = 0; j < 8; j++) s[i][j] = 0.f;

        #pragma unroll 4
        for (int d = 0; d < 64; d++) {
            float qr[8], kr[8];
            *(float4*)&qr[0] = *(const float4*)&Qt[d * 128 + ty * 8];
            *(float4*)&qr[4] = *(const float4*)&Qt[d * 128 + ty * 8 + 4];
            *(float4*)&kr[0] = *(const float4*)&Kt[d * 128 + tx * 8];
            *(float4*)&kr[4] = *(const float4*)&Kt[d * 128 + tx * 8 + 4];
            #pragma unroll
            for (int i = 0; i < 8; i++)
                #pragma unroll
                for (int j = 0; j < 8; j++)
                    s[i][j] += qr[i] * kr[j];
        }

        // online softmax per row (16 lanes with same ty own a row set)
        #pragma unroll
        for (int i = 0; i < 8; i++) {
            float mx = s[i][0];
            #pragma unroll
            for (int j = 1; j < 8; j++) mx = fmaxf(mx, s[i][j]);
            #pragma unroll
            for (int o = 8; o >= 1; o >>= 1)
                mx = fmaxf(mx, __shfl_xor_sync(0xffffffffu, mx, o));
            float mnew = fmaxf(mrow[i], mx);
            float alpha = __expf(mrow[i] - mnew);
            mrow[i] = mnew;
            float rsum = 0.f;
            #pragma unroll
            for (int j = 0; j < 8; j++) {
                float p = __expf(s[i][j] - mnew);
                s[i][j] = p;
                rsum += p;
            }
            #pragma unroll
            for (int o = 8; o >= 1; o >>= 1)
                rsum += __shfl_xor_sync(0xffffffffu, rsum, o);
            lrow[i] = lrow[i] * alpha + rsum;
            #pragma unroll
            for (int d = 0; d < 4; d++) acc[i][d] *= alpha;
            *(float4*)&Ss[(ty * 8 + i) * 128 + tx * 8]     = *(float4*)&s[i][0];
            *(float4*)&Ss[(ty * 8 + i) * 128 + tx * 8 + 4] = *(float4*)&s[i][4];
        }
        __syncthreads();

        // AV: rows ty*8..+8, dims tx*4..+4
        #pragma unroll 2
        for (int j = 0; j < 128; j += 4) {
            float pv[8][4];
            #pragma unroll
            for (int i = 0; i < 8; i++)
                *(float4*)&pv[i][0] = *(const float4*)&Ss[(ty * 8 + i) * 128 + j];
            #pragma unroll
            for (int jj = 0; jj < 4; jj++) {
                float4 vv = *(const float4*)&Vs[(j + jj) * 68 + tx * 4];
                #pragma unroll
                for (int i = 0; i < 8; i++) {
                    float p = pv[i][jj];
                    acc[i][0] += p * vv.x;
                    acc[i][1] += p * vv.y;
                    acc[i][2] += p * vv.z;
                    acc[i][3] += p * vv.w;
                }
            }
        }
    }

    // epilogue: O[row][tx*4..+4] = acc / l
    #pragma unroll
    for (int i = 0; i < 8; i++) {
        float inv = 1.f / lrow[i];
        float o[4];
        #pragma unroll
        for (int d = 0; d < 4; d++) o[d] = acc[i][d] * inv;
        float* op = O + base + (size_t)(q0 + ty * 8 + i) * DD + tx * 4;
        *(float4*)op = *(float4*)&o[0];
    }
}

// ============================================================================
// out = LayerNorm(X + Yd) * g + be  ; one row (512 floats) per block, 128 thr.
// ============================================================================
__global__ void __launch_bounds__(128)
add_ln_kernel(const float* __restrict__ X, const float* __restrict__ Yd,
              const float* __restrict__ g, const float* __restrict__ be,
              float* __restrict__ out)
{
    __shared__ float red[4];
    const int row = blockIdx.x;
    const int tid = threadIdx.x;
    const int lane = tid & 31, wid = tid >> 5;

    float4 a = ((const float4*)(X  + (size_t)row * DD))[tid];
    float4 c = ((const float4*)(Yd + (size_t)row * DD))[tid];
    float v0 = a.x + c.x, v1 = a.y + c.y, v2 = a.z + c.z, v3 = a.w + c.w;

    float sum = v0 + v1 + v2 + v3;
    #pragma unroll
    for (int o = 16; o >= 1; o >>= 1) sum += __shfl_xor_sync(0xffffffffu, sum, o);
    if (lane == 0) red[wid] = sum;
    __syncthreads();
    sum = red[0] + red[1] + red[2] + red[3];
    float mu = sum * (1.f / DD);

    float d0 = v0 - mu, d1 = v1 - mu, d2 = v2 - mu, d3 = v3 - mu;
    float sq = d0 * d0 + d1 * d1 + d2 * d2 + d3 * d3;
    #pragma unroll
    for (int o = 16; o >= 1; o >>= 1) sq += __shfl_xor_sync(0xffffffffu, sq, o);
    __syncthreads();
    if (lane == 0) red[wid] = sq;
    __syncthreads();
    float var = (red[0] + red[1] + red[2] + red[3]) * (1.f / DD);
    float rs = rsqrtf(var + 1e-5f);

    float4 gv = ((const float4*)g)[tid];
    float4 bv = ((const float4*)be)[tid];
    float4 o4;
    o4.x = d0 * rs * gv.x + bv.x;
    o4.y = d1 * rs * gv.y + bv.y;
    o4.z = d2 * rs * gv.z + bv.z;
    o4.w = d3 * rs * gv.w + bv.w;
    ((float4*)(out + (size_t)row * DD))[tid] = o4;
}

// ============================================================================
extern "C" void kernel_launch(void* const* d_in, const int* in_sizes, int n_in,
                              void* d_out, int out_size)
{
    const float* x   = (const float*)d_in[0];
    const float* wq  = (const float*)d_in[1];
    const float* bq  = (const float*)d_in[2];
    const float* wk  = (const float*)d_in[3];
    const float* bk  = (const float*)d_in[4];
    const float* wv  = (const float*)d_in[5];
    const float* bv  = (const float*)d_in[6];
    const float* wo  = (const float*)d_in[7];
    const float* bo  = (const float*)d_in[8];
    const float* w1  = (const float*)d_in[9];
    const float* b1  = (const float*)d_in[10];
    const float* w2  = (const float*)d_in[11];
    const float* b2  = (const float*)d_in[12];
    const float* g1  = (const float*)d_in[13];
    const float* be1 = (const float*)d_in[14];
    const float* g2  = (const float*)d_in[15];
    const float* be2 = (const float*)d_in[16];
    float* out = (float*)d_out;

    float *q, *k, *v, *av, *rs, *t1, *hbuf;
    cudaGetSymbolAddress((void**)&q,    g_q);
    cudaGetSymbolAddress((void**)&k,    g_k);
    cudaGetSymbolAddress((void**)&v,    g_v);
    cudaGetSymbolAddress((void**)&av,   g_av);
    cudaGetSymbolAddress((void**)&rs,   g_rs);
    cudaGetSymbolAddress((void**)&t1,   g_t1);
    cudaGetSymbolAddress((void**)&hbuf, g_h);

    cudaFuncSetAttribute(attn_kernel,
                         cudaFuncAttributeMaxDynamicSharedMemorySize,
                         ATT_SMEM_BYTES);

    dim3 blk(256);
    dim3 grid_d(DD / 128, MROWS / 128);     // (4, 64)
    dim3 grid_f(DFF / 128, MROWS / 128);    // (8, 64)

    // QKV projections
    gemm_nt_bias<false><<<grid_d, blk>>>(x, wq, bq, q, MROWS, DD, DD);
    gemm_nt_bias<false><<<grid_d, blk>>>(x, wk, bk, k, MROWS, DD, DD);
    gemm_nt_bias<false><<<grid_d, blk>>>(x, wv, bv, v, MROWS, DD, DD);

    // attention
    dim3 agrid(SS / 128, BB * HH);          // (16, 32)
    attn_kernel<<<agrid, blk, ATT_SMEM_BYTES>>>(q, k, v, av);

    // output projection + residual + LN1
    gemm_nt_bias<false><<<grid_d, blk>>>(av, wo, bo, rs, MROWS, DD, DD);
    add_ln_kernel<<<MROWS, 128>>>(x, rs, g1, be1, t1);

    // FFN
    gemm_nt_bias<true ><<<grid_f, blk>>>(t1, w1, b1, hbuf, MROWS, DFF, DD);
    gemm_nt_bias<false><<<grid_d, blk>>>(hbuf, w2, b2, rs, MROWS, DD, DFF);
    add_ln_kernel<<<MROWS, 128>>>(t1, rs, g2, be2, out);
}

// round 4
// speedup vs baseline: 2.3936x; 1.4736x over previous
#include <cuda_runtime.h>
#include <cuda_bf16.h>
#include <cstdint>
#include <math.h>

#define BB 4
#define SS 2048
#define DD 512
#define HH 8
#define DFF 1024
#define MROWS (BB*SS)

// ---------------- scratch (device globals; allocation forbidden) ------------
__device__ __align__(16) __nv_bfloat16 g_xh[MROWS*DD], g_xl[MROWS*DD];
__device__ __align__(16) __nv_bfloat16 g_wh[2097152],  g_wl[2097152];
__device__ __align__(16) __nv_bfloat16 g_qh[MROWS*DD], g_ql[MROWS*DD];
__device__ __align__(16) __nv_bfloat16 g_kh[MROWS*DD], g_kl[MROWS*DD];
__device__ __align__(16) float         g_v [MROWS*DD];
__device__ __align__(16) __nv_bfloat16 g_vth[MROWS*DD], g_vtl[MROWS*DD];
__device__ __align__(16) float         g_s [134217728];        // 32*2048*2048
__device__ __align__(16) __nv_bfloat16 g_ph[134217728], g_pl[134217728];
__device__ __align__(16) __nv_bfloat16 g_avh[MROWS*DD], g_avl[MROWS*DD];
__device__ __align__(16) float         g_rs[MROWS*DD];
__device__ __align__(16) float         g_t1[MROWS*DD];
__device__ __align__(16) __nv_bfloat16 g_t1h[MROWS*DD], g_t1l[MROWS*DD];
__device__ __align__(16) __nv_bfloat16 g_hh[MROWS*DFF], g_hl[MROWS*DFF];

#define WQ_OFF 0
#define WK_OFF 262144
#define WV_OFF 524288
#define WO_OFF 786432
#define W1_OFF 1048576
#define W2_OFF 1572864

__device__ __forceinline__ uint32_t smem_u32(const void* p) {
    uint32_t a;
    asm("{ .reg .u64 t; cvta.to.shared.u64 t, %1; cvt.u32.u64 %0, t; }" : "=r"(a) : "l"(p));
    return a;
}

#define LDSM4(r0,r1,r2,r3,addr) \
    asm volatile("ldmatrix.sync.aligned.m8n8.x4.shared.b16 {%0,%1,%2,%3}, [%4];" \
        : "=r"(r0),"=r"(r1),"=r"(r2),"=r"(r3) : "r"(addr))

#define MMA16816(c,a,b) \
    asm volatile("mma.sync.aligned.m16n8k16.row.col.f32.bf16.bf16.f32 " \
        "{%0,%1,%2,%3}, {%4,%5,%6,%7}, {%8,%9}, {%0,%1,%2,%3};" \
        : "+f"((c)[0]),"+f"((c)[1]),"+f"((c)[2]),"+f"((c)[3]) \
        : "r"((a)[0]),"r"((a)[1]),"r"((a)[2]),"r"((a)[3]), "r"((b)[0]),"r"((b)[1]))

// ---------------- split fp32 -> bf16 hi/lo ----------------------------------
__global__ void __launch_bounds__(256)
split_kernel(const float* __restrict__ s, __nv_bfloat16* __restrict__ hi,
             __nv_bfloat16* __restrict__ lo, int n4) {
    int i = blockIdx.x*256 + threadIdx.x;
    if (i >= n4) return;
    float4 v = ((const float4*)s)[i];
    __nv_bfloat162 a, b, c, d;
    a.x = __float2bfloat16(v.x); a.y = __float2bfloat16(v.y);
    b.x = __float2bfloat16(v.z); b.y = __float2bfloat16(v.w);
    c.x = __float2bfloat16(v.x - __bfloat162float(a.x));
    c.y = __float2bfloat16(v.y - __bfloat162float(a.y));
    d.x = __float2bfloat16(v.z - __bfloat162float(b.x));
    d.y = __float2bfloat16(v.w - __bfloat162float(b.y));
    uint2 u; u.x = *(uint32_t*)&a; u.y = *(uint32_t*)&b; ((uint2*)hi)[i] = u;
    uint2 w; w.x = *(uint32_t*)&c; w.y = *(uint32_t*)&d; ((uint2*)lo)[i] = w;
}

// ---------------- V transpose+split: [b,s,h*64+hd] -> [bh][hd][s] -----------
__global__ void __launch_bounds__(256)
vtrans_kernel(const float* __restrict__ v, __nv_bfloat16* __restrict__ th,
              __nv_bfloat16* __restrict__ tl) {
    __shared__ float t[64][65];
    const int tid = threadIdx.x, bh = blockIdx.y;
    const int b = bh >> 3, h = bh & 7, s0 = blockIdx.x * 64;
    for (int i = tid; i < 64*64; i += 256) {
        int sl = i >> 6, hd = i & 63;
        t[sl][hd] = v[((size_t)(b*SS + s0 + sl))*DD + h*64 + hd];
    }
    __syncthreads();
    for (int i = tid; i < 64*64; i += 256) {
        int hd = i >> 6, sl = i & 63;
        float val = t[sl][hd];
        __nv_bfloat16 hi = __float2bfloat16(val);
        size_t idx = ((size_t)bh*64 + hd)*SS + s0 + sl;
        th[idx] = hi; tl[idx] = __float2bfloat16(val - __bfloat162float(hi));
    }
}

// ---------------- softmax over rows of 2048 -> split bf16 P -----------------
__global__ void __launch_bounds__(256)
softmax_kernel(const float* __restrict__ S, __nv_bfloat16* __restrict__ Ph,
               __nv_bfloat16* __restrict__ Pl) {
    __shared__ float red[8];
    const float* sp = S + (size_t)blockIdx.x * SS;
    const int tid = threadIdx.x, lane = tid & 31, wid = tid >> 5;
    float4 v0 = ((const float4*)sp)[tid*2], v1 = ((const float4*)sp)[tid*2+1];
    float a[8] = {v0.x,v0.y,v0.z,v0.w,v1.x,v1.y,v1.z,v1.w};
    float m = a[0];
    #pragma unroll
    for (int j = 1; j < 8; j++) m = fmaxf(m, a[j]);
    #pragma unroll
    for (int o = 16; o >= 1; o >>= 1) m = fmaxf(m, __shfl_xor_sync(~0u, m, o));
    if (lane == 0) red[wid] = m;
    __syncthreads();
    float mm = red[0];
    #pragma unroll
    for (int i = 1; i < 8; i++) mm = fmaxf(mm, red[i]);
    float sum = 0.f;
    #pragma unroll
    for (int j = 0; j < 8; j++) { a[j] = __expf(a[j] - mm); sum += a[j]; }
    #pragma unroll
    for (int o = 16; o >= 1; o >>= 1) sum += __shfl_xor_sync(~0u, sum, o);
    __syncthreads();
    if (lane == 0) red[wid] = sum;
    __syncthreads();
    float tot = red[0];
    #pragma unroll
    for (int i = 1; i < 8; i++) tot += red[i];
    float inv = 1.f / tot;
    uint32_t ph[4], pl[4];
    #pragma unroll
    for (int j = 0; j < 8; j += 2) {
        float x0 = a[j]*inv, x1 = a[j+1]*inv;
        __nv_bfloat162 hh, ll;
        hh.x = __float2bfloat16(x0); hh.y = __float2bfloat16(x1);
        ll.x = __float2bfloat16(x0 - __bfloat162float(hh.x));
        ll.y = __float2bfloat16(x1 - __bfloat162float(hh.y));
        ph[j>>1] = *(uint32_t*)&hh; pl[j>>1] = *(uint32_t*)&ll;
    }
    size_t base = (size_t)blockIdx.x * SS + tid*8;
    *(uint4*)&Ph[base] = *(uint4*)ph;
    *(uint4*)&Pl[base] = *(uint4*)pl;
}

// ---------------- add + layernorm (+ optional split) ------------------------
template<bool SPLIT>
__global__ void __launch_bounds__(128)
add_ln_kernel(const float* __restrict__ X, const float* __restrict__ Y,
              const float* __restrict__ g, const float* __restrict__ be,
              float* __restrict__ out, __nv_bfloat16* oh, __nv_bfloat16* ol) {
    __shared__ float red[4];
    const int row = blockIdx.x, tid = threadIdx.x, lane = tid & 31, wid = tid >> 5;
    float4 a = ((const float4*)(X + (size_t)row*DD))[tid];
    float4 c = ((const float4*)(Y + (size_t)row*DD))[tid];
    float v0 = a.x+c.x, v1 = a.y+c.y, v2 = a.z+c.z, v3 = a.w+c.w;
    float sum = v0+v1+v2+v3;
    #pragma unroll
    for (int o = 16; o >= 1; o >>= 1) sum += __shfl_xor_sync(~0u, sum, o);
    if (lane == 0) red[wid] = sum;
    __syncthreads();
    float mu = (red[0]+red[1]+red[2]+red[3]) * (1.f/DD);
    float d0 = v0-mu, d1 = v1-mu, d2 = v2-mu, d3 = v3-mu;
    float sq = d0*d0 + d1*d1 + d2*d2 + d3*d3;
    #pragma unroll
    for (int o = 16; o >= 1; o >>= 1) sq += __shfl_xor_sync(~0u, sq, o);
    __syncthreads();
    if (lane == 0) red[wid] = sq;
    __syncthreads();
    float rsv = rsqrtf((red[0]+red[1]+red[2]+red[3]) * (1.f/DD) + 1e-5f);
    float4 gv = ((const float4*)g)[tid], bv = ((const float4*)be)[tid];
    float o0 = d0*rsv*gv.x+bv.x, o1 = d1*rsv*gv.y+bv.y;
    float o2 = d2*rsv*gv.z+bv.z, o3 = d3*rsv*gv.w+bv.w;
    float4 o4 = {o0, o1, o2, o3};
    ((float4*)(out + (size_t)row*DD))[tid] = o4;
    if (SPLIT) {
        __nv_bfloat162 ha, hb, la, lb;
        ha.x = __float2bfloat16(o0); ha.y = __float2bfloat16(o1);
        hb.x = __float2bfloat16(o2); hb.y = __float2bfloat16(o3);
        la.x = __float2bfloat16(o0 - __bfloat162float(ha.x));
        la.y = __float2bfloat16(o1 - __bfloat162float(ha.y));
        lb.x = __float2bfloat16(o2 - __bfloat162float(hb.x));
        lb.y = __float2bfloat16(o3 - __bfloat162float(hb.y));
        uint2 u; u.x = *(uint32_t*)&ha; u.y = *(uint32_t*)&hb;
        ((uint2*)(oh + (size_t)row*DD))[tid] = u;
        uint2 w; w.x = *(uint32_t*)&la; w.y = *(uint32_t*)&lb;
        ((uint2*)(ol + (size_t)row*DD))[tid] = w;
    }
}

// ============================================================================
// Split-bf16 mma.sync GEMM:  C[m][n] = sum_k A[m][k]*B[n][k]
// 3 products: AhBh + AhBl + AlBh, fp32 accumulation.
// CTA tile 128 x BN, BK=32. 8 warps: 4(M) x 2(N), warp tile 32 x BN/2.
// smem rows padded to 80B (5x16B granules) -> ldmatrix conflict-free.
// MODE 0: fp32 out (batched)   MODE 1: Q/K head-scatter split, (x+bias)*scale
// MODE 2: split out +bias(+ReLU)  MODE 3: AV remap split (batched)
// MODE 4: fp32 out +bias
// ============================================================================
template<int MODE, int BN, bool RELU>
__global__ void __launch_bounds__(256)
mgemm(const __nv_bfloat16* __restrict__ Ah, const __nv_bfloat16* __restrict__ Al,
      int lda, size_t sA,
      const __nv_bfloat16* __restrict__ Bh, const __nv_bfloat16* __restrict__ Bl,
      int ldb, size_t sB,
      float* outF, __nv_bfloat16* outH, __nv_bfloat16* outL,
      const float* __restrict__ bias, int ldo, size_t sOut, int K, float scale)
{
    constexpr int WN = BN / 2;      // warp n-extent
    constexpr int NT = WN / 8;      // n-tiles per warp (8 or 4)

    __shared__ __align__(16) char sAh[128*80];
    __shared__ __align__(16) char sAl[128*80];
    __shared__ __align__(16) char sBh[BN*80];
    __shared__ __align__(16) char sBl[BN*80];

    const int tid = threadIdx.x, wid = tid >> 5, lane = tid & 31;
    const int wm = wid & 3, wn = wid >> 2;
    const int m0 = blockIdx.y * 128, n0 = blockIdx.x * BN, z = blockIdx.z;

    const size_t ldab = (size_t)lda * 2, ldbb = (size_t)ldb * 2;
    const char* pAh = (const char*)(Ah + (size_t)z*sA) + (size_t)m0*ldab;
    const char* pAl = (const char*)(Al + (size_t)z*sA) + (size_t)m0*ldab;
    const char* pBh = (const char*)(Bh + (size_t)z*sB) + (size_t)n0*ldbb;
    const char* pBl = (const char*)(Bl + (size_t)z*sB) + (size_t)n0*ldbb;

    const uint32_t aAh = smem_u32(sAh), aAl = smem_u32(sAl);
    const uint32_t aBh = smem_u32(sBh), aBl = smem_u32(sBl);

    float acc[2][NT][4];
    #pragma unroll
    for (int mt = 0; mt < 2; mt++)
        #pragma unroll
        for (int nt = 0; nt < NT; nt++)
            #pragma unroll
            for (int r = 0; r < 4; r++) acc[mt][nt][r] = 0.f;

    const int nch = K >> 5;
    for (int kc = 0; kc < nch; ++kc) {
        const size_t kb = (size_t)kc * 64;
        #pragma unroll
        for (int i = tid; i < 512; i += 256) {
            int row = i >> 2, gg = i & 3;
            int off = row*80 + gg*16;
            *(uint4*)(sAh + off) = *(const uint4*)(pAh + (size_t)row*ldab + kb + gg*16);
            *(uint4*)(sAl + off) = *(const uint4*)(pAl + (size_t)row*ldab + kb + gg*16);
        }
        #pragma unroll
        for (int i = tid; i < BN*4; i += 256) {
            int row = i >> 2, gg = i & 3;
            int off = row*80 + gg*16;
            *(uint4*)(sBh + off) = *(const uint4*)(pBh + (size_t)row*ldbb + kb + gg*16);
            *(uint4*)(sBl + off) = *(const uint4*)(pBl + (size_t)row*ldbb + kb + gg*16);
        }
        __syncthreads();

        #pragma unroll
        for (int p = 0; p < 3; p++) {
            const uint32_t bA = (p == 2) ? aAl : aAh;
            const uint32_t bB = (p == 1) ? aBl : aBh;
            #pragma unroll
            for (int s = 0; s < 2; s++) {
                const int gsel = (s << 1) + (lane >> 4);   // k granule
                uint32_t afr[2][4];
                #pragma unroll
                for (int mt = 0; mt < 2; mt++) {
                    uint32_t ad = bA + (uint32_t)((wm*32 + mt*16 + (lane & 15))*80 + gsel*16);
                    LDSM4(afr[mt][0], afr[mt][1], afr[mt][2], afr[mt][3], ad);
                }
                uint32_t bfr[NT][2];
                #pragma unroll
                for (int np = 0; np < NT/2; np++) {
                    uint32_t r0, r1, r2, r3;
                    uint32_t ad = bB + (uint32_t)((wn*WN + np*16 + (lane & 7) + ((lane >> 3) & 1)*8)*80 + gsel*16);
                    LDSM4(r0, r1, r2, r3, ad);
                    bfr[2*np][0] = r0; bfr[2*np+1][0] = r1;
                    bfr[2*np][1] = r2; bfr[2*np+1][1] = r3;
                }
                #pragma unroll
                for (int mt = 0; mt < 2; mt++)
                    #pragma unroll
                    for (int nt = 0; nt < NT; nt++)
                        MMA16816(acc[mt][nt], afr[mt], bfr[nt]);
            }
        }
        __syncthreads();
    }

    // ---------------- epilogue -------------------------------------------
    #pragma unroll
    for (int mt = 0; mt < 2; mt++) {
        #pragma unroll
        for (int nt = 0; nt < NT; nt++) {
            int r0 = m0 + wm*32 + mt*16 + (lane >> 2);
            int r1 = r0 + 8;
            int cg = n0 + wn*WN + nt*8 + (lane & 3)*2;   // global col (even)
            #pragma unroll
            for (int half = 0; half < 2; half++) {
                int r = half ? r1 : r0;
                float x0 = acc[mt][nt][half*2 + 0];
                float x1 = acc[mt][nt][half*2 + 1];
                if constexpr (MODE == 0) {
                    float2 f2 = {x0, x1};
                    *(float2*)(outF + (size_t)z*sOut + (size_t)r*ldo + cg) = f2;
                } else if constexpr (MODE == 4) {
                    float2 f2 = {x0 + bias[cg], x1 + bias[cg+1]};
                    *(float2*)(outF + (size_t)r*ldo + cg) = f2;
                } else {
                    if constexpr (MODE == 1) {
                        x0 = (x0 + bias[cg])   * scale;
                        x1 = (x1 + bias[cg+1]) * scale;
                    }
                    if constexpr (MODE == 2) {
                        x0 += bias[cg]; x1 += bias[cg+1];
                        if (RELU) { x0 = fmaxf(x0, 0.f); x1 = fmaxf(x1, 0.f); }
                    }
                    __nv_bfloat162 hh, ll;
                    hh.x = __float2bfloat16(x0); hh.y = __float2bfloat16(x1);
                    ll.x = __float2bfloat16(x0 - __bfloat162float(hh.x));
                    ll.y = __float2bfloat16(x1 - __bfloat162float(hh.y));
                    size_t db = 0;
                    if constexpr (MODE == 1)
                        db = ((size_t)((r >> 11)*8 + (cg >> 6))*SS + (r & 2047))*64 + (cg & 63);
                    if constexpr (MODE == 2)
                        db = (size_t)r*ldo + cg;
                    if constexpr (MODE == 3)
                        db = ((size_t)((z >> 3)*SS + r))*DD + (z & 7)*64 + cg;
                    *(uint32_t*)&outH[db] = *(uint32_t*)&hh;
                    *(uint32_t*)&outL[db] = *(uint32_t*)&ll;
                }
            }
        }
    }
}

// ============================================================================
extern "C" void kernel_launch(void* const* d_in, const int* in_sizes, int n_in,
                              void* d_out, int out_size)
{
    const float* x   = (const float*)d_in[0];
    const float* wq  = (const float*)d_in[1];  const float* bq  = (const float*)d_in[2];
    const float* wk  = (const float*)d_in[3];  const float* bk  = (const float*)d_in[4];
    const float* wv  = (const float*)d_in[5];  const float* bv  = (const float*)d_in[6];
    const float* wo  = (const float*)d_in[7];  const float* bo  = (const float*)d_in[8];
    const float* w1  = (const float*)d_in[9];  const float* b1  = (const float*)d_in[10];
    const float* w2  = (const float*)d_in[11]; const float* b2  = (const float*)d_in[12];
    const float* g1  = (const float*)d_in[13]; const float* be1 = (const float*)d_in[14];
    const float* g2  = (const float*)d_in[15]; const float* be2 = (const float*)d_in[16];
    float* out = (float*)d_out;

    __nv_bfloat16 *xh,*xl,*wh,*wl,*qh,*ql,*kh,*kl,*vth,*vtl,*ph,*pl,*avh,*avl,*t1h,*t1l,*hh,*hl;
    float *v, *s, *rs, *t1;
    cudaGetSymbolAddress((void**)&xh, g_xh);  cudaGetSymbolAddress((void**)&xl, g_xl);
    cudaGetSymbolAddress((void**)&wh, g_wh);  cudaGetSymbolAddress((void**)&wl, g_wl);
    cudaGetSymbolAddress((void**)&qh, g_qh);  cudaGetSymbolAddress((void**)&ql, g_ql);
    cudaGetSymbolAddress((void**)&kh, g_kh);  cudaGetSymbolAddress((void**)&kl, g_kl);
    cudaGetSymbolAddress((void**)&v,  g_v);
    cudaGetSymbolAddress((void**)&vth, g_vth); cudaGetSymbolAddress((void**)&vtl, g_vtl);
    cudaGetSymbolAddress((void**)&s,  g_s);
    cudaGetSymbolAddress((void**)&ph, g_ph);  cudaGetSymbolAddress((void**)&pl, g_pl);
    cudaGetSymbolAddress((void**)&avh, g_avh); cudaGetSymbolAddress((void**)&avl, g_avl);
    cudaGetSymbolAddress((void**)&rs, g_rs);  cudaGetSymbolAddress((void**)&t1, g_t1);
    cudaGetSymbolAddress((void**)&t1h, g_t1h); cudaGetSymbolAddress((void**)&t1l, g_t1l);
    cudaGetSymbolAddress((void**)&hh, g_hh);  cudaGetSymbolAddress((void**)&hl, g_hl);

    dim3 blk(256);
    // splits
    split_kernel<<<4096, blk>>>(x,  xh, xl, MROWS*DD/4);
    split_kernel<<<256,  blk>>>(wq, wh+WQ_OFF, wl+WQ_OFF, 65536);
    split_kernel<<<256,  blk>>>(wk, wh+WK_OFF, wl+WK_OFF, 65536);
    split_kernel<<<256,  blk>>>(wv, wh+WV_OFF, wl+WV_OFF, 65536);
    split_kernel<<<256,  blk>>>(wo, wh+WO_OFF, wl+WO_OFF, 65536);
    split_kernel<<<512,  blk>>>(w1, wh+W1_OFF, wl+W1_OFF, 131072);
    split_kernel<<<512,  blk>>>(w2, wh+W2_OFF, wl+W2_OFF, 131072);

    // QKV projections (M=8192, N=512, K=512)
    mgemm<1,128,false><<<dim3(4,64,1), blk>>>(xh, xl, DD, 0, wh+WQ_OFF, wl+WQ_OFF, DD, 0,
        nullptr, qh, ql, bq, 0, 0, DD, 0.125f);
    mgemm<1,128,false><<<dim3(4,64,1), blk>>>(xh, xl, DD, 0, wh+WK_OFF, wl+WK_OFF, DD, 0,
        nullptr, kh, kl, bk, 0, 0, DD, 1.0f);
    mgemm<4,128,false><<<dim3(4,64,1), blk>>>(xh, xl, DD, 0, wh+WV_OFF, wl+WV_OFF, DD, 0,
        v, nullptr, nullptr, bv, DD, 0, DD, 1.0f);
    vtrans_kernel<<<dim3(32,32), blk>>>(v, vth, vtl);

    // scores: per-head Q·K^T  (M=2048, N=2048, K=64, batch=32)
    mgemm<0,128,false><<<dim3(16,16,32), blk>>>(qh, ql, 64, (size_t)SS*64,
        kh, kl, 64, (size_t)SS*64, s, nullptr, nullptr, nullptr, SS, (size_t)SS*SS, 64, 1.0f);
    softmax_kernel<<<32*SS, blk>>>(s, ph, pl);
    // P·V  (M=2048, N=64, K=2048, batch=32)
    mgemm<3,64,false><<<dim3(1,16,32), blk>>>(ph, pl, SS, (size_t)SS*SS,
        vth, vtl, SS, (size_t)64*SS, nullptr, avh, avl, nullptr, 0, 0, SS, 1.0f);

    // O projection + LN1
    mgemm<4,128,false><<<dim3(4,64,1), blk>>>(avh, avl, DD, 0, wh+WO_OFF, wl+WO_OFF, DD, 0,
        rs, nullptr, nullptr, bo, DD, 0, DD, 1.0f);
    add_ln_kernel<true><<<MROWS, 128>>>(x, rs, g1, be1, t1, t1h, t1l);

    // FFN
    mgemm<2,128,true><<<dim3(8,64,1), blk>>>(t1h, t1l, DD, 0, wh+W1_OFF, wl+W1_OFF, DD, 0,
        nullptr, hh, hl, b1, DFF, 0, DD, 1.0f);
    mgemm<4,128,false><<<dim3(4,64,1), blk>>>(hh, hl, DFF, 0, wh+W2_OFF, wl+W2_OFF, DFF, 0,
        rs, nullptr, nullptr, b2, DD, 0, DFF, 1.0f);
    add_ln_kernel<false><<<MROWS, 128>>>(t1, rs, g2, be2, out, nullptr, nullptr);
}

// round 13
// speedup vs baseline: 3.0162x; 1.2601x over previous
#include <cuda_runtime.h>
#include <cuda_bf16.h>
#include <cstdint>
#include <math.h>

#define BB 4
#define SS 2048
#define DD 512
#define HH 8
#define DFF 1024
#define MROWS (BB*SS)

// ---------------- scratch (device globals; allocation forbidden) ------------
__device__ __align__(16) __nv_bfloat16 g_xh[MROWS*DD], g_xl[MROWS*DD];
__device__ __align__(16) __nv_bfloat16 g_wh[2097152],  g_wl[2097152];
__device__ __align__(16) __nv_bfloat16 g_qh[MROWS*DD], g_ql[MROWS*DD];
__device__ __align__(16) __nv_bfloat16 g_kh[MROWS*DD], g_kl[MROWS*DD];
__device__ __align__(16) __nv_bfloat16 g_vh[MROWS*DD], g_vl[MROWS*DD];
__device__ __align__(16) __nv_bfloat16 g_avh[MROWS*DD], g_avl[MROWS*DD];
__device__ __align__(16) float         g_rs[MROWS*DD];
__device__ __align__(16) float         g_t1[MROWS*DD];
__device__ __align__(16) __nv_bfloat16 g_t1h[MROWS*DD], g_t1l[MROWS*DD];
__device__ __align__(16) __nv_bfloat16 g_hh[MROWS*DFF], g_hl[MROWS*DFF];

#define WQ_OFF 0
#define WK_OFF 262144
#define WV_OFF 524288
#define WO_OFF 786432
#define W1_OFF 1048576
#define W2_OFF 1572864

__device__ __forceinline__ uint32_t smem_u32(const void* p) {
    uint32_t a;
    asm("{ .reg .u64 t; cvta.to.shared.u64 t, %1; cvt.u32.u64 %0, t; }" : "=r"(a) : "l"(p));
    return a;
}

#define LDSM4(r0,r1,r2,r3,addr) \
    asm volatile("ldmatrix.sync.aligned.m8n8.x4.shared.b16 {%0,%1,%2,%3}, [%4];" \
        : "=r"(r0),"=r"(r1),"=r"(r2),"=r"(r3) : "r"(addr))

#define LDSM4T(r0,r1,r2,r3,addr) \
    asm volatile("ldmatrix.sync.aligned.m8n8.x4.trans.shared.b16 {%0,%1,%2,%3}, [%4];" \
        : "=r"(r0),"=r"(r1),"=r"(r2),"=r"(r3) : "r"(addr))

#define MMA16816(c,a,b) \
    asm volatile("mma.sync.aligned.m16n8k16.row.col.f32.bf16.bf16.f32 " \
        "{%0,%1,%2,%3}, {%4,%5,%6,%7}, {%8,%9}, {%0,%1,%2,%3};" \
        : "+f"((c)[0]),"+f"((c)[1]),"+f"((c)[2]),"+f"((c)[3]) \
        : "r"((a)[0]),"r"((a)[1]),"r"((a)[2]),"r"((a)[3]), "r"((b)[0]),"r"((b)[1]))

__device__ __forceinline__ uint32_t pack_hi(float x0, float x1) {
    __nv_bfloat162 h; h.x = __float2bfloat16(x0); h.y = __float2bfloat16(x1);
    return *(uint32_t*)&h;
}
__device__ __forceinline__ uint32_t pack_lo(float x0, float x1, uint32_t hi) {
    __nv_bfloat162 h = *(__nv_bfloat162*)&hi;
    __nv_bfloat162 l;
    l.x = __float2bfloat16(x0 - __bfloat162float(h.x));
    l.y = __float2bfloat16(x1 - __bfloat162float(h.y));
    return *(uint32_t*)&l;
}

// ---------------- split fp32 -> bf16 hi/lo ----------------------------------
__global__ void __launch_bounds__(256)
split_kernel(const float* __restrict__ s, __nv_bfloat16* __restrict__ hi,
             __nv_bfloat16* __restrict__ lo, int n4) {
    int i = blockIdx.x*256 + threadIdx.x;
    if (i >= n4) return;
    float4 v = ((const float4*)s)[i];
    uint2 u, w;
    u.x = pack_hi(v.x, v.y); u.y = pack_hi(v.z, v.w);
    w.x = pack_lo(v.x, v.y, u.x); w.y = pack_lo(v.z, v.w, u.y);
    ((uint2*)hi)[i] = u; ((uint2*)lo)[i] = w;
}

// ---------------- add + layernorm (+ optional split) ------------------------
template<bool SPLIT>
__global__ void __launch_bounds__(128)
add_ln_kernel(const float* __restrict__ X, const float* __restrict__ Y,
              const float* __restrict__ g, const float* __restrict__ be,
              float* __restrict__ out, __nv_bfloat16* oh, __nv_bfloat16* ol) {
    __shared__ float red[4];
    const int row = blockIdx.x, tid = threadIdx.x, lane = tid & 31, wid = tid >> 5;
    float4 a = ((const float4*)(X + (size_t)row*DD))[tid];
    float4 c = ((const float4*)(Y + (size_t)row*DD))[tid];
    float v0 = a.x+c.x, v1 = a.y+c.y, v2 = a.z+c.z, v3 = a.w+c.w;
    float sum = v0+v1+v2+v3;
    #pragma unroll
    for (int o = 16; o >= 1; o >>= 1) sum += __shfl_xor_sync(~0u, sum, o);
    if (lane == 0) red[wid] = sum;
    __syncthreads();
    float mu = (red[0]+red[1]+red[2]+red[3]) * (1.f/DD);
    float d0 = v0-mu, d1 = v1-mu, d2 = v2-mu, d3 = v3-mu;
    float sq = d0*d0 + d1*d1 + d2*d2 + d3*d3;
    #pragma unroll
    for (int o = 16; o >= 1; o >>= 1) sq += __shfl_xor_sync(~0u, sq, o);
    __syncthreads();
    if (lane == 0) red[wid] = sq;
    __syncthreads();
    float rsv = rsqrtf((red[0]+red[1]+red[2]+red[3]) * (1.f/DD) + 1e-5f);
    float4 gv = ((const float4*)g)[tid], bv = ((const float4*)be)[tid];
    float o0 = d0*rsv*gv.x+bv.x, o1 = d1*rsv*gv.y+bv.y;
    float o2 = d2*rsv*gv.z+bv.z, o3 = d3*rsv*gv.w+bv.w;
    float4 o4 = {o0, o1, o2, o3};
    ((float4*)(out + (size_t)row*DD))[tid] = o4;
    if (SPLIT) {
        uint2 u, w;
        u.x = pack_hi(o0, o1); u.y = pack_hi(o2, o3);
        w.x = pack_lo(o0, o1, u.x); w.y = pack_lo(o2, o3, u.y);
        ((uint2*)(oh + (size_t)row*DD))[tid] = u;
        ((uint2*)(ol + (size_t)row*DD))[tid] = w;
    }
}

// ============================================================================
// Split-bf16 mma.sync GEMM.  MODE 1: head-scatter split (x+b)*s
// MODE 2: split +bias(+ReLU)   MODE 4: fp32 +bias
// ============================================================================
template<int MODE, int BN, bool RELU>
__global__ void __launch_bounds__(256)
mgemm(const __nv_bfloat16* __restrict__ Ah, const __nv_bfloat16* __restrict__ Al,
      int lda,
      const __nv_bfloat16* __restrict__ Bh, const __nv_bfloat16* __restrict__ Bl,
      int ldb,
      float* outF, __nv_bfloat16* outH, __nv_bfloat16* outL,
      const float* __restrict__ bias, int ldo, int K, float scale)
{
    constexpr int WN = BN / 2;
    constexpr int NT = WN / 8;

    __shared__ __align__(16) char sAh[128*80];
    __shared__ __align__(16) char sAl[128*80];
    __shared__ __align__(16) char sBh[BN*80];
    __shared__ __align__(16) char sBl[BN*80];

    const int tid = threadIdx.x, wid = tid >> 5, lane = tid & 31;
    const int wm = wid & 3, wn = wid >> 2;
    const int m0 = blockIdx.y * 128, n0 = blockIdx.x * BN;

    const size_t ldab = (size_t)lda * 2, ldbb = (size_t)ldb * 2;
    const char* pAh = (const char*)Ah + (size_t)m0*ldab;
    const char* pAl = (const char*)Al + (size_t)m0*ldab;
    const char* pBh = (const char*)Bh + (size_t)n0*ldbb;
    const char* pBl = (const char*)Bl + (size_t)n0*ldbb;

    const uint32_t aAh = smem_u32(sAh), aAl = smem_u32(sAl);
    const uint32_t aBh = smem_u32(sBh), aBl = smem_u32(sBl);

    float acc[2][NT][4];
    #pragma unroll
    for (int mt = 0; mt < 2; mt++)
        #pragma unroll
        for (int nt = 0; nt < NT; nt++)
            #pragma unroll
            for (int r = 0; r < 4; r++) acc[mt][nt][r] = 0.f;

    const int nch = K >> 5;
    for (int kc = 0; kc < nch; ++kc) {
        const size_t kb = (size_t)kc * 64;
        #pragma unroll
        for (int i = tid; i < 512; i += 256) {
            int row = i >> 2, gg = i & 3;
            int off = row*80 + gg*16;
            *(uint4*)(sAh + off) = *(const uint4*)(pAh + (size_t)row*ldab + kb + gg*16);
            *(uint4*)(sAl + off) = *(const uint4*)(pAl + (size_t)row*ldab + kb + gg*16);
        }
        #pragma unroll
        for (int i = tid; i < BN*4; i += 256) {
            int row = i >> 2, gg = i & 3;
            int off = row*80 + gg*16;
            *(uint4*)(sBh + off) = *(const uint4*)(pBh + (size_t)row*ldbb + kb + gg*16);
            *(uint4*)(sBl + off) = *(const uint4*)(pBl + (size_t)row*ldbb + kb + gg*16);
        }
        __syncthreads();

        #pragma unroll
        for (int p = 0; p < 3; p++) {
            const uint32_t bA = (p == 2) ? aAl : aAh;
            const uint32_t bB = (p == 1) ? aBl : aBh;
            #pragma unroll
            for (int s = 0; s < 2; s++) {
                const int gsel = (s << 1) + (lane >> 4);
                uint32_t afr[2][4];
                #pragma unroll
                for (int mt = 0; mt < 2; mt++) {
                    uint32_t ad = bA + (uint32_t)((wm*32 + mt*16 + (lane & 15))*80 + gsel*16);
                    LDSM4(afr[mt][0], afr[mt][1], afr[mt][2], afr[mt][3], ad);
                }
                uint32_t bfr[NT][2];
                #pragma unroll
                for (int np = 0; np < NT/2; np++) {
                    uint32_t r0, r1, r2, r3;
                    uint32_t ad = bB + (uint32_t)((wn*WN + np*16 + (lane & 7) + ((lane >> 3) & 1)*8)*80 + gsel*16);
                    LDSM4(r0, r1, r2, r3, ad);
                    bfr[2*np][0] = r0; bfr[2*np+1][0] = r1;
                    bfr[2*np][1] = r2; bfr[2*np+1][1] = r3;
                }
                #pragma unroll
                for (int mt = 0; mt < 2; mt++)
                    #pragma unroll
                    for (int nt = 0; nt < NT; nt++)
                        MMA16816(acc[mt][nt], afr[mt], bfr[nt]);
            }
        }
        __syncthreads();
    }

    #pragma unroll
    for (int mt = 0; mt < 2; mt++) {
        #pragma unroll
        for (int nt = 0; nt < NT; nt++) {
            int r0 = m0 + wm*32 + mt*16 + (lane >> 2);
            int cg = n0 + wn*WN + nt*8 + (lane & 3)*2;
            #pragma unroll
            for (int half = 0; half < 2; half++) {
                int r = half ? (r0 + 8) : r0;
                float x0 = acc[mt][nt][half*2 + 0];
                float x1 = acc[mt][nt][half*2 + 1];
                if constexpr (MODE == 4) {
                    float2 f2 = {x0 + bias[cg], x1 + bias[cg+1]};
                    *(float2*)(outF + (size_t)r*ldo + cg) = f2;
                } else {
                    if constexpr (MODE == 1) {
                        x0 = (x0 + bias[cg])   * scale;
                        x1 = (x1 + bias[cg+1]) * scale;
                    }
                    if constexpr (MODE == 2) {
                        x0 += bias[cg]; x1 += bias[cg+1];
                        if (RELU) { x0 = fmaxf(x0, 0.f); x1 = fmaxf(x1, 0.f); }
                    }
                    uint32_t hh = pack_hi(x0, x1);
                    uint32_t ll = pack_lo(x0, x1, hh);
                    size_t db = 0;
                    if constexpr (MODE == 1)
                        db = ((size_t)((r >> 11)*8 + (cg >> 6))*SS + (r & 2047))*64 + (cg & 63);
                    if constexpr (MODE == 2)
                        db = (size_t)r*ldo + cg;
                    *(uint32_t*)&outH[db] = hh;
                    *(uint32_t*)&outL[db] = ll;
                }
            }
        }
    }
}

// ============================================================================
// Fused flash attention (split-bf16 mma.sync).
// Q/K/V in [bh][s][64] split layout. One CTA: 128 queries of one (b,h).
// 8 warps x 16 rows. K-tiles of 128 keys. Output: avh/avl [b*S+s][512].
// smem rows: 64 bf16 = 128B data + 16B pad = 144B stride (ldmatrix conflict-free).
// ============================================================================
#define FL_SZ     18432           // 128 rows * 144B
#define FL_SMEM   (6*FL_SZ)       // Qh Ql Kh Kl Vh Vl = 110592

__global__ void __launch_bounds__(256)
flash_kernel(const __nv_bfloat16* __restrict__ qh_, const __nv_bfloat16* __restrict__ ql_,
             const __nv_bfloat16* __restrict__ kh_, const __nv_bfloat16* __restrict__ kl_,
             const __nv_bfloat16* __restrict__ vh_, const __nv_bfloat16* __restrict__ vl_,
             __nv_bfloat16* __restrict__ avh, __nv_bfloat16* __restrict__ avl)
{
    extern __shared__ char fs[];
    char* sQh = fs;            char* sQl = fs + FL_SZ;
    char* sKh = fs + 2*FL_SZ;  char* sKl = fs + 3*FL_SZ;
    char* sVh = fs + 4*FL_SZ;  char* sVl = fs + 5*FL_SZ;

    const int tid = threadIdx.x, w = tid >> 5, lane = tid & 31;
    const int bh = blockIdx.y, q0 = blockIdx.x * 128;
    const size_t hbase = (size_t)bh * SS * 64;

    // load Q tile (once)
    {
        const char* pQh = (const char*)(qh_ + hbase + (size_t)q0*64);
        const char* pQl = (const char*)(ql_ + hbase + (size_t)q0*64);
        for (int i = tid; i < 1024; i += 256) {
            int r = i >> 3, g = i & 7;
            int off = r*144 + g*16;
            size_t src = (size_t)r*128 + g*16;
            *(uint4*)(sQh + off) = *(const uint4*)(pQh + src);
            *(uint4*)(sQl + off) = *(const uint4*)(pQl + src);
        }
    }

    const uint32_t aQh = smem_u32(sQh), aQl = smem_u32(sQl);
    const uint32_t aKh = smem_u32(sKh), aKl = smem_u32(sKl);
    const uint32_t aVh = smem_u32(sVh), aVl = smem_u32(sVl);

    float oa[8][4];
    #pragma unroll
    for (int nt = 0; nt < 8; nt++)
        #pragma unroll
        for (int r = 0; r < 4; r++) oa[nt][r] = 0.f;
    float m0 = -1e30f, m1 = -1e30f, l0 = 0.f, l1 = 0.f;

    for (int kt = 0; kt < SS/128; ++kt) {
        __syncthreads();
        {
            const char* pKh = (const char*)(kh_ + hbase + (size_t)kt*128*64);
            const char* pKl = (const char*)(kl_ + hbase + (size_t)kt*128*64);
            const char* pVh = (const char*)(vh_ + hbase + (size_t)kt*128*64);
            const char* pVl = (const char*)(vl_ + hbase + (size_t)kt*128*64);
            for (int i = tid; i < 1024; i += 256) {
                int r = i >> 3, g = i & 7;
                int off = r*144 + g*16;
                size_t src = (size_t)r*128 + g*16;
                *(uint4*)(sKh + off) = *(const uint4*)(pKh + src);
                *(uint4*)(sKl + off) = *(const uint4*)(pKl + src);
                *(uint4*)(sVh + off) = *(const uint4*)(pVh + src);
                *(uint4*)(sVl + off) = *(const uint4*)(pVl + src);
            }
        }
        __syncthreads();

        // ---- S = Q K^T (3 products) ----
        float sa[16][4];
        #pragma unroll
        for (int nt = 0; nt < 16; nt++)
            #pragma unroll
            for (int r = 0; r < 4; r++) sa[nt][r] = 0.f;

        #pragma unroll
        for (int p = 0; p < 3; p++) {
            const uint32_t bA = (p == 2) ? aQl : aQh;
            const uint32_t bB = (p == 1) ? aKl : aKh;
            #pragma unroll
            for (int ks = 0; ks < 4; ks++) {
                const int gsel = ks*2 + (lane >> 4);
                uint32_t af[4];
                LDSM4(af[0], af[1], af[2], af[3],
                      bA + (uint32_t)((w*16 + (lane & 15))*144 + gsel*16));
                #pragma unroll
                for (int np = 0; np < 8; np++) {
                    uint32_t r0, r1, r2, r3;
                    LDSM4(r0, r1, r2, r3,
                          bB + (uint32_t)((np*16 + (lane & 7) + ((lane >> 3) & 1)*8)*144 + gsel*16));
                    uint32_t b0[2] = {r0, r2}, b1[2] = {r1, r3};
                    MMA16816(sa[2*np],   af, b0);
                    MMA16816(sa[2*np+1], af, b1);
                }
            }
        }

        // ---- online softmax (rows r=lane>>2 and r+8 within warp tile) ----
        float tm0 = -1e30f, tm1 = -1e30f;
        #pragma unroll
        for (int nt = 0; nt < 16; nt++) {
            tm0 = fmaxf(tm0, fmaxf(sa[nt][0], sa[nt][1]));
            tm1 = fmaxf(tm1, fmaxf(sa[nt][2], sa[nt][3]));
        }
        tm0 = fmaxf(tm0, __shfl_xor_sync(~0u, tm0, 1));
        tm0 = fmaxf(tm0, __shfl_xor_sync(~0u, tm0, 2));
        tm1 = fmaxf(tm1, __shfl_xor_sync(~0u, tm1, 1));
        tm1 = fmaxf(tm1, __shfl_xor_sync(~0u, tm1, 2));
        float mn0 = fmaxf(m0, tm0), mn1 = fmaxf(m1, tm1);
        float al0 = __expf(m0 - mn0), al1 = __expf(m1 - mn1);
        float rs0 = 0.f, rs1 = 0.f;
        #pragma unroll
        for (int nt = 0; nt < 16; nt++) {
            sa[nt][0] = __expf(sa[nt][0] - mn0); rs0 += sa[nt][0];
            sa[nt][1] = __expf(sa[nt][1] - mn0); rs0 += sa[nt][1];
            sa[nt][2] = __expf(sa[nt][2] - mn1); rs1 += sa[nt][2];
            sa[nt][3] = __expf(sa[nt][3] - mn1); rs1 += sa[nt][3];
        }
        rs0 += __shfl_xor_sync(~0u, rs0, 1); rs0 += __shfl_xor_sync(~0u, rs0, 2);
        rs1 += __shfl_xor_sync(~0u, rs1, 1); rs1 += __shfl_xor_sync(~0u, rs1, 2);
        l0 = l0*al0 + rs0; l1 = l1*al1 + rs1;
        m0 = mn0; m1 = mn1;
        #pragma unroll
        for (int nt = 0; nt < 8; nt++) {
            oa[nt][0] *= al0; oa[nt][1] *= al0;
            oa[nt][2] *= al1; oa[nt][3] *= al1;
        }

        // ---- O += P V (P split in registers, V via ldmatrix.trans) ----
        #pragma unroll
        for (int ks = 0; ks < 8; ks++) {
            uint32_t ah[4], alr[4];
            ah[0]  = pack_hi(sa[2*ks][0],   sa[2*ks][1]);
            ah[1]  = pack_hi(sa[2*ks][2],   sa[2*ks][3]);
            ah[2]  = pack_hi(sa[2*ks+1][0], sa[2*ks+1][1]);
            ah[3]  = pack_hi(sa[2*ks+1][2], sa[2*ks+1][3]);
            alr[0] = pack_lo(sa[2*ks][0],   sa[2*ks][1],   ah[0]);
            alr[1] = pack_lo(sa[2*ks][2],   sa[2*ks][3],   ah[1]);
            alr[2] = pack_lo(sa[2*ks+1][0], sa[2*ks+1][1], ah[2]);
            alr[3] = pack_lo(sa[2*ks+1][2], sa[2*ks+1][3], ah[3]);
            const uint32_t voff =
                (uint32_t)((ks*16 + (lane & 7) + ((lane >> 4) & 1)*8)*144 + ((lane >> 3) & 1)*16);
            #pragma unroll
            for (int dt = 0; dt < 4; dt++) {
                uint32_t h0, h1, h2, h3, e0, e1, e2, e3;
                LDSM4T(h0, h1, h2, h3, aVh + voff + dt*32);
                LDSM4T(e0, e1, e2, e3, aVl + voff + dt*32);
                uint32_t bh0[2] = {h0, h2}, bh1[2] = {h1, h3};
                uint32_t bl0[2] = {e0, e2}, bl1[2] = {e1, e3};
                MMA16816(oa[2*dt],   ah,  bh0);
                MMA16816(oa[2*dt+1], ah,  bh1);
                MMA16816(oa[2*dt],   ah,  bl0);
                MMA16816(oa[2*dt+1], ah,  bl1);
                MMA16816(oa[2*dt],   alr, bh0);
                MMA16816(oa[2*dt+1], alr, bh1);
            }
        }
    }

    // ---- epilogue: O = oa / l, split bf16, scatter to [b*S+s][h*64+d] ----
    const int b = bh >> 3, h = bh & 7;
    const float inv0 = 1.f / l0, inv1 = 1.f / l1;
    const int rg0 = b*SS + q0 + w*16 + (lane >> 2);
    #pragma unroll
    for (int nt = 0; nt < 8; nt++) {
        int col = h*64 + nt*8 + (lane & 3)*2;
        float x0 = oa[nt][0]*inv0, x1 = oa[nt][1]*inv0;
        float y0 = oa[nt][2]*inv1, y1 = oa[nt][3]*inv1;
        uint32_t h0 = pack_hi(x0, x1), h1p = pack_hi(y0, y1);
        uint32_t l0p = pack_lo(x0, x1, h0), l1p = pack_lo(y0, y1, h1p);
        *(uint32_t*)&avh[(size_t)rg0*DD + col]       = h0;
        *(uint32_t*)&avl[(size_t)rg0*DD + col]       = l0p;
        *(uint32_t*)&avh[(size_t)(rg0+8)*DD + col]   = h1p;
        *(uint32_t*)&avl[(size_t)(rg0+8)*DD + col]   = l1p;
    }
}

// ============================================================================
extern "C" void kernel_launch(void* const* d_in, const int* in_sizes, int n_in,
                              void* d_out, int out_size)
{
    const float* x   = (const float*)d_in[0];
    const float* wq  = (const float*)d_in[1];  const float* bq  = (const float*)d_in[2];
    const float* wk  = (const float*)d_in[3];  const float* bk  = (const float*)d_in[4];
    const float* wv  = (const float*)d_in[5];  const float* bv  = (const float*)d_in[6];
    const float* wo  = (const float*)d_in[7];  const float* bo  = (const float*)d_in[8];
    const float* w1  = (const float*)d_in[9];  const float* b1  = (const float*)d_in[10];
    const float* w2  = (const float*)d_in[11]; const float* b2  = (const float*)d_in[12];
    const float* g1  = (const float*)d_in[13]; const float* be1 = (const float*)d_in[14];
    const float* g2  = (const float*)d_in[15]; const float* be2 = (const float*)d_in[16];
    float* out = (float*)d_out;

    __nv_bfloat16 *xh,*xl,*wh,*wl,*qh,*ql,*kh,*kl,*vh,*vl,*avh,*avl,*t1h,*t1l,*hh,*hl;
    float *rs, *t1;
    cudaGetSymbolAddress((void**)&xh, g_xh);  cudaGetSymbolAddress((void**)&xl, g_xl);
    cudaGetSymbolAddress((void**)&wh, g_wh);  cudaGetSymbolAddress((void**)&wl, g_wl);
    cudaGetSymbolAddress((void**)&qh, g_qh);  cudaGetSymbolAddress((void**)&ql, g_ql);
    cudaGetSymbolAddress((void**)&kh, g_kh);  cudaGetSymbolAddress((void**)&kl, g_kl);
    cudaGetSymbolAddress((void**)&vh, g_vh);  cudaGetSymbolAddress((void**)&vl, g_vl);
    cudaGetSymbolAddress((void**)&avh, g_avh); cudaGetSymbolAddress((void**)&avl, g_avl);
    cudaGetSymbolAddress((void**)&rs, g_rs);  cudaGetSymbolAddress((void**)&t1, g_t1);
    cudaGetSymbolAddress((void**)&t1h, g_t1h); cudaGetSymbolAddress((void**)&t1l, g_t1l);
    cudaGetSymbolAddress((void**)&hh, g_hh);  cudaGetSymbolAddress((void**)&hl, g_hl);

    cudaFuncSetAttribute(flash_kernel,
                         cudaFuncAttributeMaxDynamicSharedMemorySize, FL_SMEM);

    dim3 blk(256);
    // splits
    split_kernel<<<4096, blk>>>(x,  xh, xl, MROWS*DD/4);
    split_kernel<<<256,  blk>>>(wq, wh+WQ_OFF, wl+WQ_OFF, 65536);
    split_kernel<<<256,  blk>>>(wk, wh+WK_OFF, wl+WK_OFF, 65536);
    split_kernel<<<256,  blk>>>(wv, wh+WV_OFF, wl+WV_OFF, 65536);
    split_kernel<<<256,  blk>>>(wo, wh+WO_OFF, wl+WO_OFF, 65536);
    split_kernel<<<512,  blk>>>(w1, wh+W1_OFF, wl+W1_OFF, 131072);
    split_kernel<<<512,  blk>>>(w2, wh+W2_OFF, wl+W2_OFF, 131072);

    // QKV projections -> split head layout [bh][s][64]; softmax scale folded into Q
    mgemm<1,128,false><<<dim3(4,64), blk>>>(xh, xl, DD, wh+WQ_OFF, wl+WQ_OFF, DD,
        nullptr, qh, ql, bq, 0, DD, 0.125f);
    mgemm<1,128,false><<<dim3(4,64), blk>>>(xh, xl, DD, wh+WK_OFF, wl+WK_OFF, DD,
        nullptr, kh, kl, bk, 0, DD, 1.0f);
    mgemm<1,128,false><<<dim3(4,64), blk>>>(xh, xl, DD, wh+WV_OFF, wl+WV_OFF, DD,
        nullptr, vh, vl, bv, 0, DD, 1.0f);

    // fused flash attention
    flash_kernel<<<dim3(SS/128, BB*HH), blk, FL_SMEM>>>(qh, ql, kh, kl, vh, vl, avh, avl);

    // O projection + LN1
    mgemm<4,128,false><<<dim3(4,64), blk>>>(avh, avl, DD, wh+WO_OFF, wl+WO_OFF, DD,
        rs, nullptr, nullptr, bo, DD, DD, 1.0f);
    add_ln_kernel<true><<<MROWS, 128>>>(x, rs, g1, be1, t1, t1h, t1l);

    // FFN
    mgemm<2,128,true><<<dim3(8,64), blk>>>(t1h, t1l, DD, wh+W1_OFF, wl+W1_OFF, DD,
        nullptr, hh, hl, b1, DFF, DD, 1.0f);
    mgemm<4,128,false><<<dim3(4,64), blk>>>(hh, hl, DFF, wh+W2_OFF, wl+W2_OFF, DFF,
        rs, nullptr, nullptr, b2, DD, DFF, 1.0f);
    add_ln_kernel<false><<<MROWS, 128>>>(t1, rs, g2, be2, out, nullptr, nullptr);
}

// round 17
// speedup vs baseline: 3.3291x; 1.1037x over previous
#include <cuda_runtime.h>
#include <cuda_bf16.h>
#include <cstdint>
#include <math.h>

#define BB 4
#define SS 2048
#define DD 512
#define HH 8
#define DFF 1024
#define MROWS (BB*SS)

// ---------------- scratch (device globals; allocation forbidden) ------------
__device__ __align__(16) __nv_bfloat16 g_xh[MROWS*DD], g_xl[MROWS*DD];
__device__ __align__(16) __nv_bfloat16 g_wh[2097152],  g_wl[2097152];
__device__ __align__(16) __nv_bfloat16 g_qh[MROWS*DD], g_ql[MROWS*DD];
__device__ __align__(16) __nv_bfloat16 g_kh[MROWS*DD], g_kl[MROWS*DD];
__device__ __align__(16) __nv_bfloat16 g_vh[MROWS*DD], g_vl[MROWS*DD];
__device__ __align__(16) __nv_bfloat16 g_avh[MROWS*DD], g_avl[MROWS*DD];
__device__ __align__(16) float         g_rs[MROWS*DD];
__device__ __align__(16) float         g_t1[MROWS*DD];
__device__ __align__(16) __nv_bfloat16 g_t1h[MROWS*DD], g_t1l[MROWS*DD];
__device__ __align__(16) __nv_bfloat16 g_hh[MROWS*DFF], g_hl[MROWS*DFF];

#define WQ_OFF 0
#define WK_OFF 262144
#define WV_OFF 524288
#define WO_OFF 786432
#define W1_OFF 1048576
#define W2_OFF 1572864

__device__ __forceinline__ uint32_t smem_u32(const void* p) {
    uint32_t a;
    asm("{ .reg .u64 t; cvta.to.shared.u64 t, %1; cvt.u32.u64 %0, t; }" : "=r"(a) : "l"(p));
    return a;
}

#define LDSM4(r0,r1,r2,r3,addr) \
    asm volatile("ldmatrix.sync.aligned.m8n8.x4.shared.b16 {%0,%1,%2,%3}, [%4];" \
        : "=r"(r0),"=r"(r1),"=r"(r2),"=r"(r3) : "r"(addr))

#define LDSM4T(r0,r1,r2,r3,addr) \
    asm volatile("ldmatrix.sync.aligned.m8n8.x4.trans.shared.b16 {%0,%1,%2,%3}, [%4];" \
        : "=r"(r0),"=r"(r1),"=r"(r2),"=r"(r3) : "r"(addr))

#define MMA16816(c,a,b) \
    asm volatile("mma.sync.aligned.m16n8k16.row.col.f32.bf16.bf16.f32 " \
        "{%0,%1,%2,%3}, {%4,%5,%6,%7}, {%8,%9}, {%0,%1,%2,%3};" \
        : "+f"((c)[0]),"+f"((c)[1]),"+f"((c)[2]),"+f"((c)[3]) \
        : "r"((a)[0]),"r"((a)[1]),"r"((a)[2]),"r"((a)[3]), "r"((b)[0]),"r"((b)[1]))

#define CP_A16(dst, src) \
    asm volatile("cp.async.cg.shared.global [%0], [%1], 16;" :: "r"(dst), "l"(src))
#define CP_COMMIT() asm volatile("cp.async.commit_group;" ::: "memory")
#define CP_WAIT1()  asm volatile("cp.async.wait_group 1;" ::: "memory")
#define CP_WAIT0()  asm volatile("cp.async.wait_group 0;" ::: "memory")

__device__ __forceinline__ uint32_t pack_hi(float x0, float x1) {
    __nv_bfloat162 h; h.x = __float2bfloat16(x0); h.y = __float2bfloat16(x1);
    return *(uint32_t*)&h;
}
__device__ __forceinline__ uint32_t pack_lo(float x0, float x1, uint32_t hi) {
    __nv_bfloat162 h = *(__nv_bfloat162*)&hi;
    __nv_bfloat162 l;
    l.x = __float2bfloat16(x0 - __bfloat162float(h.x));
    l.y = __float2bfloat16(x1 - __bfloat162float(h.y));
    return *(uint32_t*)&l;
}

// ---------------- split fp32 -> bf16 hi/lo ----------------------------------
__global__ void __launch_bounds__(256)
split_kernel(const float* __restrict__ s, __nv_bfloat16* __restrict__ hi,
             __nv_bfloat16* __restrict__ lo, int n4) {
    int i = blockIdx.x*256 + threadIdx.x;
    if (i >= n4) return;
    float4 v = ((const float4*)s)[i];
    uint2 u, w;
    u.x = pack_hi(v.x, v.y); u.y = pack_hi(v.z, v.w);
    w.x = pack_lo(v.x, v.y, u.x); w.y = pack_lo(v.z, v.w, u.y);
    ((uint2*)hi)[i] = u; ((uint2*)lo)[i] = w;
}

// ---------------- add + layernorm (+ optional split) ------------------------
template<bool SPLIT>
__global__ void __launch_bounds__(128)
add_ln_kernel(const float* __restrict__ X, const float* __restrict__ Y,
              const float* __restrict__ g, const float* __restrict__ be,
              float* __restrict__ out, __nv_bfloat16* oh, __nv_bfloat16* ol) {
    __shared__ float red[4];
    const int row = blockIdx.x, tid = threadIdx.x, lane = tid & 31, wid = tid >> 5;
    float4 a = ((const float4*)(X + (size_t)row*DD))[tid];
    float4 c = ((const float4*)(Y + (size_t)row*DD))[tid];
    float v0 = a.x+c.x, v1 = a.y+c.y, v2 = a.z+c.z, v3 = a.w+c.w;
    float sum = v0+v1+v2+v3;
    #pragma unroll
    for (int o = 16; o >= 1; o >>= 1) sum += __shfl_xor_sync(~0u, sum, o);
    if (lane == 0) red[wid] = sum;
    __syncthreads();
    float mu = (red[0]+red[1]+red[2]+red[3]) * (1.f/DD);
    float d0 = v0-mu, d1 = v1-mu, d2 = v2-mu, d3 = v3-mu;
    float sq = d0*d0 + d1*d1 + d2*d2 + d3*d3;
    #pragma unroll
    for (int o = 16; o >= 1; o >>= 1) sq += __shfl_xor_sync(~0u, sq, o);
    __syncthreads();
    if (lane == 0) red[wid] = sq;
    __syncthreads();
    float rsv = rsqrtf((red[0]+red[1]+red[2]+red[3]) * (1.f/DD) + 1e-5f);
    float4 gv = ((const float4*)g)[tid], bv = ((const float4*)be)[tid];
    float o0 = d0*rsv*gv.x+bv.x, o1 = d1*rsv*gv.y+bv.y;
    float o2 = d2*rsv*gv.z+bv.z, o3 = d3*rsv*gv.w+bv.w;
    float4 o4 = {o0, o1, o2, o3};
    ((float4*)(out + (size_t)row*DD))[tid] = o4;
    if (SPLIT) {
        uint2 u, w;
        u.x = pack_hi(o0, o1); u.y = pack_hi(o2, o3);
        w.x = pack_lo(o0, o1, u.x); w.y = pack_lo(o2, o3, u.y);
        ((uint2*)(oh + (size_t)row*DD))[tid] = u;
        ((uint2*)(ol + (size_t)row*DD))[tid] = w;
    }
}

// ============================================================================
// Split-bf16 mma.sync GEMM (UNCHANGED — verified correct at R4/R13).
// MODE 1: head-scatter split (x+b)*s  MODE 2: split +bias(+ReLU)  MODE 4: fp32 +bias
// ============================================================================
template<int MODE, int BN, bool RELU>
__global__ void __launch_bounds__(256)
mgemm(const __nv_bfloat16* __restrict__ Ah, const __nv_bfloat16* __restrict__ Al,
      int lda,
      const __nv_bfloat16* __restrict__ Bh, const __nv_bfloat16* __restrict__ Bl,
      int ldb,
      float* outF, __nv_bfloat16* outH, __nv_bfloat16* outL,
      const float* __restrict__ bias, int ldo, int K, float scale)
{
    constexpr int WN = BN / 2;
    constexpr int NT = WN / 8;

    __shared__ __align__(16) char sAh[128*80];
    __shared__ __align__(16) char sAl[128*80];
    __shared__ __align__(16) char sBh[BN*80];
    __shared__ __align__(16) char sBl[BN*80];

    const int tid = threadIdx.x, wid = tid >> 5, lane = tid & 31;
    const int wm = wid & 3, wn = wid >> 2;
    const int m0 = blockIdx.y * 128, n0 = blockIdx.x * BN;

    const size_t ldab = (size_t)lda * 2, ldbb = (size_t)ldb * 2;
    const char* pAh = (const char*)Ah + (size_t)m0*ldab;
    const char* pAl = (const char*)Al + (size_t)m0*ldab;
    const char* pBh = (const char*)Bh + (size_t)n0*ldbb;
    const char* pBl = (const char*)Bl + (size_t)n0*ldbb;

    const uint32_t aAh = smem_u32(sAh), aAl = smem_u32(sAl);
    const uint32_t aBh = smem_u32(sBh), aBl = smem_u32(sBl);

    float acc[2][NT][4];
    #pragma unroll
    for (int mt = 0; mt < 2; mt++)
        #pragma unroll
        for (int nt = 0; nt < NT; nt++)
            #pragma unroll
            for (int r = 0; r < 4; r++) acc[mt][nt][r] = 0.f;

    const int nch = K >> 5;
    for (int kc = 0; kc < nch; ++kc) {
        const size_t kb = (size_t)kc * 64;
        #pragma unroll
        for (int i = tid; i < 512; i += 256) {
            int row = i >> 2, gg = i & 3;
            int off = row*80 + gg*16;
            *(uint4*)(sAh + off) = *(const uint4*)(pAh + (size_t)row*ldab + kb + gg*16);
            *(uint4*)(sAl + off) = *(const uint4*)(pAl + (size_t)row*ldab + kb + gg*16);
        }
        #pragma unroll
        for (int i = tid; i < BN*4; i += 256) {
            int row = i >> 2, gg = i & 3;
            int off = row*80 + gg*16;
            *(uint4*)(sBh + off) = *(const uint4*)(pBh + (size_t)row*ldbb + kb + gg*16);
            *(uint4*)(sBl + off) = *(const uint4*)(pBl + (size_t)row*ldbb + kb + gg*16);
        }
        __syncthreads();

        #pragma unroll
        for (int p = 0; p < 3; p++) {
            const uint32_t bA = (p == 2) ? aAl : aAh;
            const uint32_t bB = (p == 1) ? aBl : aBh;
            #pragma unroll
            for (int s = 0; s < 2; s++) {
                const int gsel = (s << 1) + (lane >> 4);
                uint32_t afr[2][4];
                #pragma unroll
                for (int mt = 0; mt < 2; mt++) {
                    uint32_t ad = bA + (uint32_t)((wm*32 + mt*16 + (lane & 15))*80 + gsel*16);
                    LDSM4(afr[mt][0], afr[mt][1], afr[mt][2], afr[mt][3], ad);
                }
                uint32_t bfr[NT][2];
                #pragma unroll
                for (int np = 0; np < NT/2; np++) {
                    uint32_t r0, r1, r2, r3;
                    uint32_t ad = bB + (uint32_t)((wn*WN + np*16 + (lane & 7) + ((lane >> 3) & 1)*8)*80 + gsel*16);
                    LDSM4(r0, r1, r2, r3, ad);
                    bfr[2*np][0] = r0; bfr[2*np+1][0] = r1;
                    bfr[2*np][1] = r2; bfr[2*np+1][1] = r3;
                }
                #pragma unroll
                for (int mt = 0; mt < 2; mt++)
                    #pragma unroll
                    for (int nt = 0; nt < NT; nt++)
                        MMA16816(acc[mt][nt], afr[mt], bfr[nt]);
            }
        }
        __syncthreads();
    }

    #pragma unroll
    for (int mt = 0; mt < 2; mt++) {
        #pragma unroll
        for (int nt = 0; nt < NT; nt++) {
            int r0 = m0 + wm*32 + mt*16 + (lane >> 2);
            int cg = n0 + wn*WN + nt*8 + (lane & 3)*2;
            #pragma unroll
            for (int half = 0; half < 2; half++) {
                int r = half ? (r0 + 8) : r0;
                float x0 = acc[mt][nt][half*2 + 0];
                float x1 = acc[mt][nt][half*2 + 1];
                if constexpr (MODE == 4) {
                    float2 f2 = {x0 + bias[cg], x1 + bias[cg+1]};
                    *(float2*)(outF + (size_t)r*ldo + cg) = f2;
                } else {
                    if constexpr (MODE == 1) {
                        x0 = (x0 + bias[cg])   * scale;
                        x1 = (x1 + bias[cg+1]) * scale;
                    }
                    if constexpr (MODE == 2) {
                        x0 += bias[cg]; x1 += bias[cg+1];
                        if (RELU) { x0 = fmaxf(x0, 0.f); x1 = fmaxf(x1, 0.f); }
                    }
                    uint32_t hh = pack_hi(x0, x1);
                    uint32_t ll = pack_lo(x0, x1, hh);
                    size_t db = 0;
                    if constexpr (MODE == 1)
                        db = ((size_t)((r >> 11)*8 + (cg >> 6))*SS + (r & 2047))*64 + (cg & 63);
                    if constexpr (MODE == 2)
                        db = (size_t)r*ldo + cg;
                    *(uint32_t*)&outH[db] = hh;
                    *(uint32_t*)&outL[db] = ll;
                }
            }
        }
    }
}

// ============================================================================
// Fused flash attention: 2-stage cp.async pipeline on K/V tiles.
// FIX vs R14-16: prefetch byte offset = tile * 16384 BYTES (was element count).
// smem: Qh Ql (resident) + 2 stages x (Kh Kl Vh Vl) = 180 KB.
// ============================================================================
#define FL_SZ      18432                 // 128 rows * 144B
#define FL_STAGE   (4*FL_SZ)             // Kh Kl Vh Vl per stage
#define FL_SMEM    (2*FL_SZ + 2*FL_STAGE)  // 184320 B
#define TILE_BYTES 16384                 // 128 rows * 64 elems * 2B

__global__ void __launch_bounds__(256)
flash_kernel(const __nv_bfloat16* __restrict__ qh_, const __nv_bfloat16* __restrict__ ql_,
             const __nv_bfloat16* __restrict__ kh_, const __nv_bfloat16* __restrict__ kl_,
             const __nv_bfloat16* __restrict__ vh_, const __nv_bfloat16* __restrict__ vl_,
             __nv_bfloat16* __restrict__ avh, __nv_bfloat16* __restrict__ avl)
{
    extern __shared__ char fs[];
    const uint32_t sb = smem_u32(fs);
    const uint32_t aQh = sb, aQl = sb + FL_SZ;

    const int tid = threadIdx.x, w = tid >> 5, lane = tid & 31;
    const int bh = blockIdx.y, q0 = blockIdx.x * 128;
    const size_t hbase = (size_t)bh * SS * 64;

    const char* gQh = (const char*)(qh_ + hbase + (size_t)q0*64);
    const char* gQl = (const char*)(ql_ + hbase + (size_t)q0*64);
    const char* gKh = (const char*)(kh_ + hbase);
    const char* gKl = (const char*)(kl_ + hbase);
    const char* gVh = (const char*)(vh_ + hbase);
    const char* gVl = (const char*)(vl_ + hbase);

    // group 0: Q tiles + K/V tiles for kt=0 into stage 0
    {
        for (int i = tid; i < 1024; i += 256) {
            int r = i >> 3, g = i & 7;
            uint32_t off = (uint32_t)(r*144 + g*16);
            size_t src = (size_t)r*128 + g*16;
            CP_A16(aQh + off, gQh + src);
            CP_A16(aQl + off, gQl + src);
        }
        const uint32_t s0 = sb + 2*FL_SZ;
        for (int i = tid; i < 1024; i += 256) {
            int r = i >> 3, g = i & 7;
            uint32_t off = (uint32_t)(r*144 + g*16);
            size_t src = (size_t)r*128 + g*16;
            CP_A16(s0 + 0*FL_SZ + off, gKh + src);
            CP_A16(s0 + 1*FL_SZ + off, gKl + src);
            CP_A16(s0 + 2*FL_SZ + off, gVh + src);
            CP_A16(s0 + 3*FL_SZ + off, gVl + src);
        }
        CP_COMMIT();
    }

    float oa[8][4];
    #pragma unroll
    for (int nt = 0; nt < 8; nt++)
        #pragma unroll
        for (int r = 0; r < 4; r++) oa[nt][r] = 0.f;
    float m0 = -1e30f, m1 = -1e30f, l0 = 0.f, l1 = 0.f;

    for (int kt = 0; kt < SS/128; ++kt) {
        // issue next tile into the other stage
        if (kt + 1 < SS/128) {
            const uint32_t sn = sb + 2*FL_SZ + ((kt + 1) & 1)*FL_STAGE;
            const size_t kbase = (size_t)(kt + 1)*TILE_BYTES;   // BYTES (fixed)
            for (int i = tid; i < 1024; i += 256) {
                int r = i >> 3, g = i & 7;
                uint32_t off = (uint32_t)(r*144 + g*16);
                size_t src = kbase + (size_t)r*128 + g*16;
                CP_A16(sn + 0*FL_SZ + off, gKh + src);
                CP_A16(sn + 1*FL_SZ + off, gKl + src);
                CP_A16(sn + 2*FL_SZ + off, gVh + src);
                CP_A16(sn + 3*FL_SZ + off, gVl + src);
            }
            CP_COMMIT();
            CP_WAIT1();     // current tile's group done
        } else {
            CP_WAIT0();
        }
        __syncthreads();

        const uint32_t sc = sb + 2*FL_SZ + (kt & 1)*FL_STAGE;
        const uint32_t aKh = sc, aKl = sc + FL_SZ;
        const uint32_t aVh = sc + 2*FL_SZ, aVl = sc + 3*FL_SZ;

        // ---- S = Q K^T (3 products) ----
        float sa[16][4];
        #pragma unroll
        for (int nt = 0; nt < 16; nt++)
            #pragma unroll
            for (int r = 0; r < 4; r++) sa[nt][r] = 0.f;

        #pragma unroll
        for (int p = 0; p < 3; p++) {
            const uint32_t bA = (p == 2) ? aQl : aQh;
            const uint32_t bB = (p == 1) ? aKl : aKh;
            #pragma unroll
            for (int ks = 0; ks < 4; ks++) {
                const int gsel = ks*2 + (lane >> 4);
                uint32_t af[4];
                LDSM4(af[0], af[1], af[2], af[3],
                      bA + (uint32_t)((w*16 + (lane & 15))*144 + gsel*16));
                #pragma unroll
                for (int np = 0; np < 8; np++) {
                    uint32_t r0, r1, r2, r3;
                    LDSM4(r0, r1, r2, r3,
                          bB + (uint32_t)((np*16 + (lane & 7) + ((lane >> 3) & 1)*8)*144 + gsel*16));
                    uint32_t b0[2] = {r0, r2}, b1[2] = {r1, r3};
                    MMA16816(sa[2*np],   af, b0);
                    MMA16816(sa[2*np+1], af, b1);
                }
            }
        }

        // ---- online softmax ----
        float tm0 = -1e30f, tm1 = -1e30f;
        #pragma unroll
        for (int nt = 0; nt < 16; nt++) {
            tm0 = fmaxf(tm0, fmaxf(sa[nt][0], sa[nt][1]));
            tm1 = fmaxf(tm1, fmaxf(sa[nt][2], sa[nt][3]));
        }
        tm0 = fmaxf(tm0, __shfl_xor_sync(~0u, tm0, 1));
        tm0 = fmaxf(tm0, __shfl_xor_sync(~0u, tm0, 2));
        tm1 = fmaxf(tm1, __shfl_xor_sync(~0u, tm1, 1));
        tm1 = fmaxf(tm1, __shfl_xor_sync(~0u, tm1, 2));
        float mn0 = fmaxf(m0, tm0), mn1 = fmaxf(m1, tm1);
        float al0 = __expf(m0 - mn0), al1 = __expf(m1 - mn1);
        float rs0 = 0.f, rs1 = 0.f;
        #pragma unroll
        for (int nt = 0; nt < 16; nt++) {
            sa[nt][0] = __expf(sa[nt][0] - mn0); rs0 += sa[nt][0];
            sa[nt][1] = __expf(sa[nt][1] - mn0); rs0 += sa[nt][1];
            sa[nt][2] = __expf(sa[nt][2] - mn1); rs1 += sa[nt][2];
            sa[nt][3] = __expf(sa[nt][3] - mn1); rs1 += sa[nt][3];
        }
        rs0 += __shfl_xor_sync(~0u, rs0, 1); rs0 += __shfl_xor_sync(~0u, rs0, 2);
        rs1 += __shfl_xor_sync(~0u, rs1, 1); rs1 += __shfl_xor_sync(~0u, rs1, 2);
        l0 = l0*al0 + rs0; l1 = l1*al1 + rs1;
        m0 = mn0; m1 = mn1;
        #pragma unroll
        for (int nt = 0; nt < 8; nt++) {
            oa[nt][0] *= al0; oa[nt][1] *= al0;
            oa[nt][2] *= al1; oa[nt][3] *= al1;
        }

        // ---- O += P V ----
        #pragma unroll
        for (int ks = 0; ks < 8; ks++) {
            uint32_t ah[4], alr[4];
            ah[0]  = pack_hi(sa[2*ks][0],   sa[2*ks][1]);
            ah[1]  = pack_hi(sa[2*ks][2],   sa[2*ks][3]);
            ah[2]  = pack_hi(sa[2*ks+1][0], sa[2*ks+1][1]);
            ah[3]  = pack_hi(sa[2*ks+1][2], sa[2*ks+1][3]);
            alr[0] = pack_lo(sa[2*ks][0],   sa[2*ks][1],   ah[0]);
            alr[1] = pack_lo(sa[2*ks][2],   sa[2*ks][3],   ah[1]);
            alr[2] = pack_lo(sa[2*ks+1][0], sa[2*ks+1][1], ah[2]);
            alr[3] = pack_lo(sa[2*ks+1][2], sa[2*ks+1][3], ah[3]);
            const uint32_t voff =
                (uint32_t)((ks*16 + (lane & 7) + ((lane >> 4) & 1)*8)*144 + ((lane >> 3) & 1)*16);
            #pragma unroll
            for (int dt = 0; dt < 4; dt++) {
                uint32_t h0, h1, h2, h3, e0, e1, e2, e3;
                LDSM4T(h0, h1, h2, h3, aVh + voff + dt*32);
                LDSM4T(e0, e1, e2, e3, aVl + voff + dt*32);
                uint32_t bh0[2] = {h0, h2}, bh1[2] = {h1, h3};
                uint32_t bl0[2] = {e0, e2}, bl1[2] = {e1, e3};
                MMA16816(oa[2*dt],   ah,  bh0);
                MMA16816(oa[2*dt+1], ah,  bh1);
                MMA16816(oa[2*dt],   ah,  bl0);
                MMA16816(oa[2*dt+1], ah,  bl1);
                MMA16816(oa[2*dt],   alr, bh0);
                MMA16816(oa[2*dt+1], alr, bh1);
            }
        }
        __syncthreads();   // stage reused by the issue at top of iteration kt+2
    }

    // ---- epilogue ----
    const int b = bh >> 3, h = bh & 7;
    const float inv0 = 1.f / l0, inv1 = 1.f / l1;
    const int rg0 = b*SS + q0 + w*16 + (lane >> 2);
    #pragma unroll
    for (int nt = 0; nt < 8; nt++) {
        int col = h*64 + nt*8 + (lane & 3)*2;
        float x0 = oa[nt][0]*inv0, x1 = oa[nt][1]*inv0;
        float y0 = oa[nt][2]*inv1, y1 = oa[nt][3]*inv1;
        uint32_t h0 = pack_hi(x0, x1), h1p = pack_hi(y0, y1);
        uint32_t l0p = pack_lo(x0, x1, h0), l1p = pack_lo(y0, y1, h1p);
        *(uint32_t*)&avh[(size_t)rg0*DD + col]       = h0;
        *(uint32_t*)&avl[(size_t)rg0*DD + col]       = l0p;
        *(uint32_t*)&avh[(size_t)(rg0+8)*DD + col]   = h1p;
        *(uint32_t*)&avl[(size_t)(rg0+8)*DD + col]   = l1p;
    }
}

// ============================================================================
extern "C" void kernel_launch(void* const* d_in, const int* in_sizes, int n_in,
                              void* d_out, int out_size)
{
    const float* x   = (const float*)d_in[0];
    const float* wq  = (const float*)d_in[1];  const float* bq  = (const float*)d_in[2];
    const float* wk  = (const float*)d_in[3];  const float* bk  = (const float*)d_in[4];
    const float* wv  = (const float*)d_in[5];  const float* bv  = (const float*)d_in[6];
    const float* wo  = (const float*)d_in[7];  const float* bo  = (const float*)d_in[8];
    const float* w1  = (const float*)d_in[9];  const float* b1  = (const float*)d_in[10];
    const float* w2  = (const float*)d_in[11]; const float* b2  = (const float*)d_in[12];
    const float* g1  = (const float*)d_in[13]; const float* be1 = (const float*)d_in[14];
    const float* g2  = (const float*)d_in[15]; const float* be2 = (const float*)d_in[16];
    float* out = (float*)d_out;

    __nv_bfloat16 *xh,*xl,*wh,*wl,*qh,*ql,*kh,*kl,*vh,*vl,*avh,*avl,*t1h,*t1l,*hh,*hl;
    float *rs, *t1;
    cudaGetSymbolAddress((void**)&xh, g_xh);  cudaGetSymbolAddress((void**)&xl, g_xl);
    cudaGetSymbolAddress((void**)&wh, g_wh);  cudaGetSymbolAddress((void**)&wl, g_wl);
    cudaGetSymbolAddress((void**)&qh, g_qh);  cudaGetSymbolAddress((void**)&ql, g_ql);
    cudaGetSymbolAddress((void**)&kh, g_kh);  cudaGetSymbolAddress((void**)&kl, g_kl);
    cudaGetSymbolAddress((void**)&vh, g_vh);  cudaGetSymbolAddress((void**)&vl, g_vl);
    cudaGetSymbolAddress((void**)&avh, g_avh); cudaGetSymbolAddress((void**)&avl, g_avl);
    cudaGetSymbolAddress((void**)&rs, g_rs);  cudaGetSymbolAddress((void**)&t1, g_t1);
    cudaGetSymbolAddress((void**)&t1h, g_t1h); cudaGetSymbolAddress((void**)&t1l, g_t1l);
    cudaGetSymbolAddress((void**)&hh, g_hh);  cudaGetSymbolAddress((void**)&hl, g_hl);

    cudaFuncSetAttribute(flash_kernel,
                         cudaFuncAttributeMaxDynamicSharedMemorySize, FL_SMEM);

    dim3 blk(256);
    // splits
    split_kernel<<<4096, blk>>>(x,  xh, xl, MROWS*DD/4);
    split_kernel<<<256,  blk>>>(wq, wh+WQ_OFF, wl+WQ_OFF, 65536);
    split_kernel<<<256,  blk>>>(wk, wh+WK_OFF, wl+WK_OFF, 65536);
    split_kernel<<<256,  blk>>>(wv, wh+WV_OFF, wl+WV_OFF, 65536);
    split_kernel<<<256,  blk>>>(wo, wh+WO_OFF, wl+WO_OFF, 65536);
    split_kernel<<<512,  blk>>>(w1, wh+W1_OFF, wl+W1_OFF, 131072);
    split_kernel<<<512,  blk>>>(w2, wh+W2_OFF, wl+W2_OFF, 131072);

    // QKV projections -> split head layout [bh][s][64]; softmax scale folded into Q
    mgemm<1,128,false><<<dim3(4,64), blk>>>(xh, xl, DD, wh+WQ_OFF, wl+WQ_OFF, DD,
        nullptr, qh, ql, bq, 0, DD, 0.125f);
    mgemm<1,128,false><<<dim3(4,64), blk>>>(xh, xl, DD, wh+WK_OFF, wl+WK_OFF, DD,
        nullptr, kh, kl, bk, 0, DD, 1.0f);
    mgemm<1,128,false><<<dim3(4,64), blk>>>(xh, xl, DD, wh+WV_OFF, wl+WV_OFF, DD,
        nullptr, vh, vl, bv, 0, DD, 1.0f);

    // fused flash attention (cp.async pipelined, prefetch offset fixed)
    flash_kernel<<<dim3(SS/128, BB*HH), blk, FL_SMEM>>>(qh, ql, kh, kl, vh, vl, avh, avl);

    // O projection + LN1
    mgemm<4,128,false><<<dim3(4,64), blk>>>(avh, avl, DD, wh+WO_OFF, wl+WO_OFF, DD,
        rs, nullptr, nullptr, bo, DD, DD, 1.0f);
    add_ln_kernel<true><<<MROWS, 128>>>(x, rs, g1, be1, t1, t1h, t1l);

    // FFN
    mgemm<2,128,true><<<dim3(8,64), blk>>>(t1h, t1l, DD, wh+W1_OFF, wl+W1_OFF, DD,
        nullptr, hh, hl, b1, DFF, DD, 1.0f);
    mgemm<4,128,false><<<dim3(4,64), blk>>>(hh, hl, DFF, wh+W2_OFF, wl+W2_OFF, DFF,
        rs, nullptr, nullptr, b2, DD, DFF, 1.0f);
    add_ln_kernel<false><<<MROWS, 128>>>(t1, rs, g2, be2, out, nullptr, nullptr);
}